// round 3
// baseline (speedup 1.0000x reference)
#include <cuda_runtime.h>
#include <math.h>
#include <stdint.h>

// Problem dims
#define Bb   256
#define Tt   256
#define INP  2
#define Ss   2
#define Hh   1024
#define Zz   1026      // S + H
#define KW   1028      // WU_w inner dim = IN + S + H

// Output buffer layout (flattened pytree of the reference return):
// outputs (B,T,Z) | zf (1,B,Z) | czf (1,B,Z) | coefficients (B,T,S) | mats (T,2,2)
#define OUT_OFF  0ll
#define ZF_OFF   ((long long)Bb * Tt * Zz)
#define CZF_OFF  (ZF_OFF + (long long)Bb * Zz)
#define COEF_OFF (CZF_OFF + (long long)Bb * Zz)
#define MATS_OFF (COEF_OFF + (long long)Bb * Tt * Ss)

// Persistent state (device globals — no allocation allowed)
__device__ float g_h[2][Bb * Hh];   // ping-pong hidden state
__device__ float g_c[Bb * Hh];      // cell state (in-place update)
__device__ float g_x[Bb * Ss];      // dynamical state

__device__ __forceinline__ float sigm(float x) {
    return 1.0f / (1.0f + expf(-x));
}

// ---------------------------------------------------------------------------
// init: load z0 / c_z0 into state buffers
// ---------------------------------------------------------------------------
__global__ void init_state(const float* __restrict__ z0,
                           const float* __restrict__ c_z0) {
    int i = blockIdx.x * blockDim.x + threadIdx.x;
    if (i < Bb * Hh) {
        int b = i / Hh, j = i - b * Hh;
        g_h[0][i] = z0[(size_t)b * Zz + 2 + j];
        g_c[i]    = c_z0[(size_t)b * Zz + 2 + j];
    }
    if (i < Bb * Ss) {
        int b = i / Ss, s = i - b * Ss;
        g_x[i] = z0[(size_t)b * Zz + s];
    }
}

// ---------------------------------------------------------------------------
// Kernel A: gates GEMM (h @ Wh^T) fused with x/input columns, bias,
// and the full LSTM pointwise update. Each CTA: 64 batch rows x 16 hidden
// units (i.e. 64x64 gate values, all 4 gates per hidden unit).
// Grid: (B/64, H/16) = (4, 64). Block: 128 threads.
// ---------------------------------------------------------------------------
#define BM   64
#define BHU  16
#define BK   32
#define HPAD 68
#define WPAD 68

__global__ __launch_bounds__(128) void gates_lstm(
    const float* __restrict__ WU_w,      // (4096, 1028) row-major
    const float* __restrict__ WU_b,      // (4096)
    const float* __restrict__ rnn_input, // (B, T, IN)
    float* __restrict__ out,             // d_out
    int t)
{
    __shared__ float sh_h[BK][HPAD];     // [k][m]
    __shared__ float sh_w[BK][WPAD];     // [k][n*4+g]

    const float* __restrict__ h_in  = g_h[t & 1];
    float*       __restrict__ h_out = g_h[(t & 1) ^ 1];

    int tid = threadIdx.x;
    int tx  = tid & 7;    // 2 hidden units each
    int ty  = tid >> 3;   // 4 batch rows each (0..15)
    int m0  = blockIdx.x * BM;
    int n0  = blockIdx.y * BHU;

    float acc[4][2][4];
    #pragma unroll
    for (int mi = 0; mi < 4; mi++)
        #pragma unroll
        for (int ni = 0; ni < 2; ni++)
            #pragma unroll
            for (int g = 0; g < 4; g++)
                acc[mi][ni][g] = 0.0f;

    for (int k0 = 0; k0 < Hh; k0 += BK) {
        // load h tile: 64 rows x 32 k  (512 float4, 4 per thread)
        #pragma unroll
        for (int it = 0; it < 4; it++) {
            int f  = tid + it * 128;
            int m  = f >> 3;
            int kk = f & 7;
            float4 v = *reinterpret_cast<const float4*>(
                &h_in[(size_t)(m0 + m) * Hh + k0 + kk * 4]);
            sh_h[kk * 4 + 0][m] = v.x;
            sh_h[kk * 4 + 1][m] = v.y;
            sh_h[kk * 4 + 2][m] = v.z;
            sh_h[kk * 4 + 3][m] = v.w;
        }
        // load W tile: 64 gate-rows x 32 k
        #pragma unroll
        for (int it = 0; it < 4; it++) {
            int f   = tid + it * 128;
            int row = f >> 3;            // g*16 + n
            int kk  = f & 7;
            int g   = row >> 4;
            int n   = row & 15;
            int j   = g * Hh + n0 + n;   // global gate row in WU_w
            float4 v = *reinterpret_cast<const float4*>(
                &WU_w[(size_t)j * KW + 4 + k0 + kk * 4]);
            int col = n * 4 + g;
            sh_w[kk * 4 + 0][col] = v.x;
            sh_w[kk * 4 + 1][col] = v.y;
            sh_w[kk * 4 + 2][col] = v.z;
            sh_w[kk * 4 + 3][col] = v.w;
        }
        __syncthreads();

        #pragma unroll
        for (int k = 0; k < BK; k++) {
            float4 hv  = *reinterpret_cast<const float4*>(&sh_h[k][ty * 4]);
            float4 wa  = *reinterpret_cast<const float4*>(&sh_w[k][tx * 8]);
            float4 wb4 = *reinterpret_cast<const float4*>(&sh_w[k][tx * 8 + 4]);
            float hm[4] = {hv.x, hv.y, hv.z, hv.w};
            float w0[4] = {wa.x, wa.y, wa.z, wa.w};
            float w1[4] = {wb4.x, wb4.y, wb4.z, wb4.w};
            #pragma unroll
            for (int mi = 0; mi < 4; mi++) {
                #pragma unroll
                for (int g = 0; g < 4; g++) {
                    acc[mi][0][g] = fmaf(hm[mi], w0[g], acc[mi][0][g]);
                    acc[mi][1][g] = fmaf(hm[mi], w1[g], acc[mi][1][g]);
                }
            }
        }
        __syncthreads();
    }

    // Epilogue: add x_prev/input columns + bias, apply LSTM pointwise.
    float xp0[4], xp1[4], in0v[4], in1v[4];
    #pragma unroll
    for (int mi = 0; mi < 4; mi++) {
        int b    = m0 + ty * 4 + mi;
        xp0[mi]  = g_x[b * 2 + 0];
        xp1[mi]  = g_x[b * 2 + 1];
        size_t ib = (size_t)b * Tt * INP + (size_t)t * INP;
        in0v[mi] = rnn_input[ib + 0];
        in1v[mi] = rnn_input[ib + 1];
    }

    #pragma unroll
    for (int ni = 0; ni < 2; ni++) {
        int n = n0 + tx * 2 + ni;
        float bias[4];
        float4 wx[4];
        #pragma unroll
        for (int g = 0; g < 4; g++) {
            int j   = g * Hh + n;
            bias[g] = WU_b[j];
            wx[g]   = *reinterpret_cast<const float4*>(&WU_w[(size_t)j * KW]);
        }
        #pragma unroll
        for (int mi = 0; mi < 4; mi++) {
            int b = m0 + ty * 4 + mi;
            float gate[4];
            #pragma unroll
            for (int g = 0; g < 4; g++) {
                gate[g] = acc[mi][ni][g] + bias[g]
                        + xp0[mi] * wx[g].x + xp1[mi] * wx[g].y
                        + in0v[mi] * wx[g].z + in1v[mi] * wx[g].w;
            }
            float ig = sigm(gate[0]);
            float fg = sigm(gate[1]);
            float gg = tanhf(gate[2]);
            float og = sigm(gate[3]);
            int idx  = b * Hh + n;
            float cn = fg * g_c[idx] + ig * gg;
            g_c[idx] = cn;
            float hn = og * tanhf(cn);
            h_out[idx] = hn;
            out[(size_t)b * Tt * Zz + (size_t)t * Zz + 2 + n] = hn;
        }
    }
}

// ---------------------------------------------------------------------------
// Kernel B: alpha/Wx projections (4 dots of length 1024 per batch row) +
// Van-der-Pol dynamics + x update + outputs/coefficients/mats writes.
// Grid: (B). Block: 128 threads.
// ---------------------------------------------------------------------------
__global__ __launch_bounds__(128) void alpha_x(
    const float* __restrict__ alpha_w, const float* __restrict__ alpha_b,
    const float* __restrict__ Wx_w,    const float* __restrict__ Wx_b,
    const float* __restrict__ rnn_input, const float* __restrict__ tau,
    float* __restrict__ out, int t)
{
    int b   = blockIdx.x;
    int tid = threadIdx.x;
    const float* __restrict__ h = g_h[(t & 1) ^ 1] + (size_t)b * Hh;

    float s0 = 0.f, s1 = 0.f, s2 = 0.f, s3 = 0.f;
    for (int k = tid; k < Hh; k += 128) {
        float hv = h[k];
        s0 = fmaf(hv, alpha_w[k],      s0);
        s1 = fmaf(hv, alpha_w[Hh + k], s1);
        s2 = fmaf(hv, Wx_w[k],         s2);
        s3 = fmaf(hv, Wx_w[Hh + k],    s3);
    }
    #pragma unroll
    for (int off = 16; off > 0; off >>= 1) {
        s0 += __shfl_down_sync(0xffffffffu, s0, off);
        s1 += __shfl_down_sync(0xffffffffu, s1, off);
        s2 += __shfl_down_sync(0xffffffffu, s2, off);
        s3 += __shfl_down_sync(0xffffffffu, s3, off);
    }
    __shared__ float red[4][4];
    if ((tid & 31) == 0) {
        int w = tid >> 5;
        red[w][0] = s0; red[w][1] = s1; red[w][2] = s2; red[w][3] = s3;
    }
    __syncthreads();
    if (tid == 0) {
        s0 = red[0][0] + red[1][0] + red[2][0] + red[3][0];
        s1 = red[0][1] + red[1][1] + red[2][1] + red[3][1];
        s2 = red[0][2] + red[1][2] + red[2][2] + red[3][2];
        s3 = red[0][3] + red[1][3] + red[2][3] + red[3][3];

        float x1 = g_x[b * 2 + 0];
        float x2 = g_x[b * 2 + 1];
        float u  = rnn_input[(size_t)b * Tt * INP + (size_t)t * INP];  // inp[:, :1]
        float ta = tau[(size_t)b * Tt + t];

        float a10 = -1.0f - 2.0f * x1 * x2;      // MHU = 1, DYN = 1
        float a11 = 1.0f - x1 * x1;
        float dx0 = x2;
        float dx1 = a10 * x1 + a11 * x2 + u;     // B_mat = [[0],[1]]
        float xm0 = x1 + ta * dx0;
        float xm1 = x2 + ta * dx1;

        float al0 = sigm(s0 + alpha_b[0]);
        float al1 = sigm(s1 + alpha_b[1]);
        float xn0 = (1.0f - al0) * xm0 + al0 * (s2 + Wx_b[0]);
        float xn1 = (1.0f - al1) * xm1 + al1 * (s3 + Wx_b[1]);

        g_x[b * 2 + 0] = xn0;
        g_x[b * 2 + 1] = xn1;

        size_t ob = (size_t)b * Tt * Zz + (size_t)t * Zz;
        out[ob + 0] = xn0;
        out[ob + 1] = xn1;
        size_t cb = COEF_OFF + (size_t)b * Tt * Ss + (size_t)t * Ss;
        out[cb + 0] = al0;
        out[cb + 1] = al1;
        if (b == 0) {
            size_t mb = MATS_OFF + (size_t)t * 4;
            out[mb + 0] = 0.0f;
            out[mb + 1] = 1.0f;
            out[mb + 2] = a10;
            out[mb + 3] = a11;
        }
    }
}

// ---------------------------------------------------------------------------
// finalize: zf = [x_final, h_final], czf = [c_z0[:, :2], c_final]
// ---------------------------------------------------------------------------
__global__ void finalize(const float* __restrict__ c_z0,
                         float* __restrict__ out) {
    int i = blockIdx.x * blockDim.x + threadIdx.x;
    if (i >= Bb * Zz) return;
    int b = i / Zz, z = i - b * Zz;
    float zv, cv;
    if (z < 2) {
        zv = g_x[b * 2 + z];
        cv = c_z0[(size_t)b * Zz + z];
    } else {
        // T=256 steps: step t writes g_h[(t+1)&1]; t=255 -> g_h[0]
        zv = g_h[0][(size_t)b * Hh + z - 2];
        cv = g_c[(size_t)b * Hh + z - 2];
    }
    out[ZF_OFF  + i] = zv;
    out[CZF_OFF + i] = cv;
}

// ---------------------------------------------------------------------------
extern "C" void kernel_launch(void* const* d_in, const int* in_sizes, int n_in,
                              void* d_out, int out_size) {
    const float* rnn_input = (const float*)d_in[0];
    const float* tau       = (const float*)d_in[1];
    const float* z0        = (const float*)d_in[2];
    const float* c_z0      = (const float*)d_in[3];
    const float* WU_w      = (const float*)d_in[4];
    const float* WU_b      = (const float*)d_in[5];
    const float* alpha_w   = (const float*)d_in[6];
    const float* alpha_b   = (const float*)d_in[7];
    const float* Wx_w      = (const float*)d_in[8];
    const float* Wx_b      = (const float*)d_in[9];
    float* out = (float*)d_out;

    init_state<<<(Bb * Hh + 255) / 256, 256>>>(z0, c_z0);

    dim3 gridA(Bb / BM, Hh / BHU);   // (4, 64)
    for (int t = 0; t < Tt; t++) {
        gates_lstm<<<gridA, 128>>>(WU_w, WU_b, rnn_input, out, t);
        alpha_x<<<Bb, 128>>>(alpha_w, alpha_b, Wx_w, Wx_b,
                             rnn_input, tau, out, t);
    }
    finalize<<<(Bb * Zz + 127) / 128, 128>>>(c_z0, out);
}

// round 6
// speedup vs baseline: 2.4787x; 2.4787x over previous
#include <cuda_runtime.h>
#include <cuda_bf16.h>
#include <math.h>
#include <stdint.h>

#define Bb   256
#define Tt   256
#define Hh   1024
#define Zz   1026
#define KW   1028

#define ZF_OFF   ((long long)Bb * Tt * Zz)
#define CZF_OFF  (ZF_OFF + (long long)Bb * Zz)
#define COEF_OFF (CZF_OFF + (long long)Bb * Zz)
#define MATS_OFF (COEF_OFF + (long long)Bb * Tt * 2)

// Persistent device state
__device__ float g_h[2][Bb * Hh];
__device__ float g_c[Bb * Hh];
__device__ float g_x[Bb * 2];
// Pre-swizzled bf16 weight images: [nb 0..63][chunk 0..15][hi 4096 bf16 | lo 4096 bf16]
__device__ __align__(128) __nv_bfloat16 g_Wimg[64 * 16 * 8192];
__device__ float g_bias[4096];          // gate-interleaved bias
__device__ float g_wfront[4096 * 4];    // exact fp32 first-4 columns, interleaved

__device__ __forceinline__ float sigm(float x) { return 1.0f / (1.0f + expf(-x)); }

__device__ __forceinline__ uint32_t smem_u32(const void* p) {
    uint32_t a;
    asm("{ .reg .u64 t; cvta.to.shared.u64 t, %1; cvt.u32.u64 %0, t; }" : "=r"(a) : "l"(p));
    return a;
}

__device__ __forceinline__ void ldsm4(uint32_t* r, uint32_t addr) {
    asm volatile("ldmatrix.sync.aligned.m8n8.x4.shared.b16 {%0,%1,%2,%3}, [%4];"
                 : "=r"(r[0]), "=r"(r[1]), "=r"(r[2]), "=r"(r[3]) : "r"(addr));
}

__device__ __forceinline__ void mma16816(float (&d)[4], const uint32_t* a,
                                         uint32_t b0, uint32_t b1) {
    asm volatile(
        "mma.sync.aligned.m16n8k16.row.col.f32.bf16.bf16.f32 "
        "{%0,%1,%2,%3}, {%4,%5,%6,%7}, {%8,%9}, {%0,%1,%2,%3};"
        : "+f"(d[0]), "+f"(d[1]), "+f"(d[2]), "+f"(d[3])
        : "r"(a[0]), "r"(a[1]), "r"(a[2]), "r"(a[3]), "r"(b0), "r"(b1));
}

#define BUFSZ 32768   // Ah 8K | Al 8K | Bh 8K | Bl 8K
#define DSTRIDE 66

// ---------------------------------------------------------------------------
// repack: W -> gate-interleaved, hi/lo bf16, pre-swizzled SMEM image
// ---------------------------------------------------------------------------
__global__ void repack(const float* __restrict__ WU_w) {
    int nb = blockIdx.x, ch = blockIdx.y;
    size_t base = (size_t)(nb * 16 + ch) * 8192;
    for (int e = threadIdx.x; e < 4096; e += 256) {
        int r = e >> 6, c = e & 63;
        int rg = nb * 64 + r;
        int u = rg >> 2, g = rg & 3;
        float w = WU_w[(size_t)(g * Hh + u) * KW + 4 + ch * 64 + c];
        __nv_bfloat16 hi = __float2bfloat16_rn(w);
        __nv_bfloat16 lo = __float2bfloat16_rn(w - __bfloat162float(hi));
        uint32_t off = (uint32_t)(r * 128 + c * 2);
        off ^= (off >> 3) & 0x70;
        g_Wimg[base + (off >> 1)] = hi;
        g_Wimg[base + 4096 + (off >> 1)] = lo;
    }
}

__global__ void prep_misc(const float* __restrict__ WU_w,
                          const float* __restrict__ WU_b) {
    int r = blockIdx.x * 256 + threadIdx.x;
    if (r >= 4096) return;
    int u = r >> 2, g = r & 3;
    g_bias[r] = WU_b[g * Hh + u];
    const float* src = WU_w + (size_t)(g * Hh + u) * KW;
    #pragma unroll
    for (int j = 0; j < 4; j++) g_wfront[r * 4 + j] = src[j];
}

__global__ void init_state(const float* __restrict__ z0,
                           const float* __restrict__ c_z0) {
    int i = blockIdx.x * blockDim.x + threadIdx.x;
    if (i < Bb * Hh) {
        int b = i / Hh, j = i - b * Hh;
        g_h[0][i] = z0[(size_t)b * Zz + 2 + j];
        g_c[i]    = c_z0[(size_t)b * Zz + 2 + j];
    }
    if (i < Bb * 2) {
        int b = i >> 1, s = i & 1;
        g_x[i] = z0[(size_t)b * Zz + s];
    }
}

// ---------------------------------------------------------------------------
// Stage A (h tile 64x64, split hi/lo, swizzled) + B (identity cp.async)
// ---------------------------------------------------------------------------
__device__ __forceinline__ void stage(char* smb, uint32_t sb,
                                      const float* __restrict__ hin,
                                      int m0, int nb, int tid, int ch, int buf) {
    char* ah = smb + buf * BUFSZ;
    char* al = ah + 8192;
    const int k0 = ch * 64;
    #pragma unroll
    for (int it = 0; it < 4; it++) {
        int f = it * 128 + tid;
        int row = f >> 3;
        int csb = (f & 7) * 16;                 // byte col within 128B row
        const float* src = hin + (size_t)(m0 + row) * Hh + k0 + (f & 7) * 8;
        float4 a = *(const float4*)src;
        float4 b = *(const float4*)(src + 4);
        float v[8] = {a.x, a.y, a.z, a.w, b.x, b.y, b.z, b.w};
        uint32_t hiw[4], low[4];
        #pragma unroll
        for (int q = 0; q < 4; q++) {
            __nv_bfloat162 h2 = __float22bfloat162_rn(make_float2(v[2*q], v[2*q+1]));
            float2 bk = __bfloat1622float2(h2);
            __nv_bfloat162 l2 = __float22bfloat162_rn(
                make_float2(v[2*q] - bk.x, v[2*q+1] - bk.y));
            hiw[q] = *(uint32_t*)&h2;
            low[q] = *(uint32_t*)&l2;
        }
        uint32_t rel = (uint32_t)(row * 128) + ((uint32_t)csb ^ ((row & 7) << 4));
        *(uint4*)(ah + rel) = make_uint4(hiw[0], hiw[1], hiw[2], hiw[3]);
        *(uint4*)(al + rel) = make_uint4(low[0], low[1], low[2], low[3]);
    }
    // B: 16KB identity copy (hi 8K | lo 8K), pre-swizzled in g_Wimg
    uint32_t bdst = sb + buf * BUFSZ + 16384;
    const char* wsrc = (const char*)(g_Wimg + (size_t)(nb * 16 + ch) * 8192);
    #pragma unroll
    for (int it = 0; it < 8; it++) {
        int f = it * 128 + tid;
        asm volatile("cp.async.cg.shared.global [%0], [%1], 16;"
                     :: "r"(bdst + f * 16), "l"(wsrc + f * 16) : "memory");
    }
}

// ---------------------------------------------------------------------------
// Gates GEMM via mma.sync bf16 3-pass + fused LSTM pointwise.
// Grid (4, 64), block 128 (4 warps). CTA tile: 64 batch x 64 gate-cols.
// ---------------------------------------------------------------------------
__global__ __launch_bounds__(128) void gates_mma(
    const float* __restrict__ rnn_input, float* __restrict__ out, int t)
{
    extern __shared__ char smraw[];
    uint32_t sb0 = smem_u32(smraw);
    uint32_t pad = (128u - (sb0 & 127u)) & 127u;
    char* smb = smraw + pad;
    uint32_t sb = sb0 + pad;

    int tid = threadIdx.x;
    int m0 = blockIdx.x * 64, nb = blockIdx.y;
    const float* hin = g_h[t & 1];
    float* hout = g_h[(t & 1) ^ 1];

    stage(smb, sb, hin, m0, nb, tid, 0, 0);
    asm volatile("cp.async.commit_group;" ::: "memory");

    float acc[8][4];
    #pragma unroll
    for (int j = 0; j < 8; j++)
        #pragma unroll
        for (int q = 0; q < 4; q++) acc[j][q] = 0.0f;

    int w = tid >> 5, lane = tid & 31;
    int arow = w * 16 + (lane & 15);
    uint32_t a_roff = (uint32_t)arow * 128;
    uint32_t a_kx   = (uint32_t)((lane >> 4) * 16);
    uint32_t a_xm   = (uint32_t)((arow & 7) << 4);
    int brow = (lane & 7) + ((lane >> 4) & 1) * 8;
    uint32_t b_kx = (uint32_t)(((lane >> 3) & 1) * 16);
    uint32_t b_xm = (uint32_t)((lane & 7) << 4);

    for (int c = 0; c < 16; c++) {
        int buf = c & 1;
        if (c + 1 < 16) {
            stage(smb, sb, hin, m0, nb, tid, c + 1, buf ^ 1);
            asm volatile("cp.async.commit_group;" ::: "memory");
            asm volatile("cp.async.wait_group 1;" ::: "memory");
        } else {
            asm volatile("cp.async.wait_group 0;" ::: "memory");
        }
        __syncthreads();

        uint32_t ab  = sb + buf * BUFSZ;
        uint32_t ahi = ab, alo = ab + 8192;
        uint32_t bhi = ab + 16384, blo = ab + 24576;

        #pragma unroll
        for (int kk = 0; kk < 4; kk++) {
            uint32_t kofs = (uint32_t)(kk * 32);
            uint32_t aoff = a_roff + ((a_kx + kofs) ^ a_xm);
            uint32_t Ah[4], Al[4];
            ldsm4(Ah, ahi + aoff);
            ldsm4(Al, alo + aoff);
            #pragma unroll
            for (int p = 0; p < 4; p++) {
                uint32_t boff = (uint32_t)((p * 16 + brow) * 128)
                              + ((b_kx + kofs) ^ b_xm);
                uint32_t Bh[4], Bl[4];
                ldsm4(Bh, bhi + boff);
                ldsm4(Bl, blo + boff);
                mma16816(acc[2*p],     Ah, Bh[0], Bh[1]);
                mma16816(acc[2*p + 1], Ah, Bh[2], Bh[3]);
                mma16816(acc[2*p],     Al, Bh[0], Bh[1]);
                mma16816(acc[2*p + 1], Al, Bh[2], Bh[3]);
                mma16816(acc[2*p],     Ah, Bl[0], Bl[1]);
                mma16816(acc[2*p + 1], Ah, Bl[2], Bl[3]);
            }
        }
        __syncthreads();
    }

    // Store accumulators to smem D (overlaps buf0; last compute used buf1)
    float* D = (float*)smb;
    int r0 = w * 16 + (lane >> 2);
    int c0b = (lane & 3) * 2;
    #pragma unroll
    for (int j = 0; j < 8; j++) {
        int c0 = j * 8 + c0b;
        *(float2*)&D[r0 * DSTRIDE + c0]       = make_float2(acc[j][0], acc[j][1]);
        *(float2*)&D[(r0 + 8) * DSTRIDE + c0] = make_float2(acc[j][2], acc[j][3]);
    }
    __syncthreads();

    // Pointwise: thread -> (row = tid>>1, 8 units)
    int row = tid >> 1;
    int ub  = (tid & 1) * 8;
    int b   = m0 + row;
    float xp0 = g_x[b * 2], xp1 = g_x[b * 2 + 1];
    const float* ibp = rnn_input + (size_t)b * Tt * 2 + (size_t)t * 2;
    float in0 = ibp[0], in1 = ibp[1];

    float* cptr = g_c + (size_t)b * Hh + nb * 16 + ub;
    float* hp   = hout + (size_t)b * Hh + nb * 16 + ub;
    float* op   = out + (size_t)b * Tt * Zz + (size_t)t * Zz + 2 + nb * 16 + ub;

    float cc[8], hnv[8];
    #pragma unroll
    for (int q = 0; q < 2; q++) {
        float4 v = *(float4*)(cptr + q * 4);
        cc[4*q] = v.x; cc[4*q+1] = v.y; cc[4*q+2] = v.z; cc[4*q+3] = v.w;
    }
    #pragma unroll
    for (int q = 0; q < 8; q++) {
        int ul = ub + q;
        int rg = nb * 64 + ul * 4;
        float4 bias = *(const float4*)(g_bias + rg);
        float bv[4] = {bias.x, bias.y, bias.z, bias.w};
        float gv[4];
        #pragma unroll
        for (int g2 = 0; g2 < 4; g2++) {
            float4 wf = *(const float4*)(g_wfront + (size_t)(rg + g2) * 4);
            gv[g2] = D[row * DSTRIDE + ul * 4 + g2] + bv[g2]
                   + xp0 * wf.x + xp1 * wf.y + in0 * wf.z + in1 * wf.w;
        }
        float ig = sigm(gv[0]), fg = sigm(gv[1]);
        float gg = tanhf(gv[2]), og = sigm(gv[3]);
        float cn = fg * cc[q] + ig * gg;
        cc[q] = cn;
        hnv[q] = og * tanhf(cn);
    }
    #pragma unroll
    for (int q = 0; q < 2; q++) {
        *(float4*)(cptr + q * 4) = make_float4(cc[4*q], cc[4*q+1], cc[4*q+2], cc[4*q+3]);
        *(float4*)(hp + q * 4)   = make_float4(hnv[4*q], hnv[4*q+1], hnv[4*q+2], hnv[4*q+3]);
    }
    // out row is only 8-byte aligned (Zz = 1026) -> float2 stores
    #pragma unroll
    for (int q = 0; q < 4; q++)
        *(float2*)(op + q * 2) = make_float2(hnv[2*q], hnv[2*q+1]);
}

// ---------------------------------------------------------------------------
__global__ __launch_bounds__(128) void alpha_x(
    const float* __restrict__ alpha_w, const float* __restrict__ alpha_b,
    const float* __restrict__ Wx_w,    const float* __restrict__ Wx_b,
    const float* __restrict__ rnn_input, const float* __restrict__ tau,
    float* __restrict__ out, int t)
{
    int b = blockIdx.x, tid = threadIdx.x;
    const float* __restrict__ h = g_h[(t & 1) ^ 1] + (size_t)b * Hh;
    float s0 = 0.f, s1 = 0.f, s2 = 0.f, s3 = 0.f;
    for (int k = tid; k < Hh; k += 128) {
        float hv = h[k];
        s0 = fmaf(hv, alpha_w[k],      s0);
        s1 = fmaf(hv, alpha_w[Hh + k], s1);
        s2 = fmaf(hv, Wx_w[k],         s2);
        s3 = fmaf(hv, Wx_w[Hh + k],    s3);
    }
    #pragma unroll
    for (int off = 16; off > 0; off >>= 1) {
        s0 += __shfl_down_sync(0xffffffffu, s0, off);
        s1 += __shfl_down_sync(0xffffffffu, s1, off);
        s2 += __shfl_down_sync(0xffffffffu, s2, off);
        s3 += __shfl_down_sync(0xffffffffu, s3, off);
    }
    __shared__ float red[4][4];
    if ((tid & 31) == 0) {
        int w = tid >> 5;
        red[w][0] = s0; red[w][1] = s1; red[w][2] = s2; red[w][3] = s3;
    }
    __syncthreads();
    if (tid == 0) {
        s0 = red[0][0] + red[1][0] + red[2][0] + red[3][0];
        s1 = red[0][1] + red[1][1] + red[2][1] + red[3][1];
        s2 = red[0][2] + red[1][2] + red[2][2] + red[3][2];
        s3 = red[0][3] + red[1][3] + red[2][3] + red[3][3];

        float x1 = g_x[b * 2 + 0], x2 = g_x[b * 2 + 1];
        float u  = rnn_input[(size_t)b * Tt * 2 + (size_t)t * 2];
        float ta = tau[(size_t)b * Tt + t];
        float a10 = -1.0f - 2.0f * x1 * x2;
        float a11 = 1.0f - x1 * x1;
        float xm0 = x1 + ta * x2;
        float xm1 = x2 + ta * (a10 * x1 + a11 * x2 + u);
        float al0 = sigm(s0 + alpha_b[0]);
        float al1 = sigm(s1 + alpha_b[1]);
        float xn0 = (1.0f - al0) * xm0 + al0 * (s2 + Wx_b[0]);
        float xn1 = (1.0f - al1) * xm1 + al1 * (s3 + Wx_b[1]);
        g_x[b * 2 + 0] = xn0;
        g_x[b * 2 + 1] = xn1;

        size_t ob = (size_t)b * Tt * Zz + (size_t)t * Zz;
        out[ob + 0] = xn0;
        out[ob + 1] = xn1;
        size_t cb = COEF_OFF + (size_t)b * Tt * 2 + (size_t)t * 2;
        out[cb + 0] = al0;
        out[cb + 1] = al1;
        if (b == 0) {
            size_t mb = MATS_OFF + (size_t)t * 4;
            out[mb + 0] = 0.0f;
            out[mb + 1] = 1.0f;
            out[mb + 2] = a10;
            out[mb + 3] = a11;
        }
    }
}

__global__ void finalize(const float* __restrict__ c_z0,
                         float* __restrict__ out) {
    int i = blockIdx.x * blockDim.x + threadIdx.x;
    if (i >= Bb * Zz) return;
    int b = i / Zz, z = i - b * Zz;
    float zv, cv;
    if (z < 2) {
        zv = g_x[b * 2 + z];
        cv = c_z0[(size_t)b * Zz + z];
    } else {
        zv = g_h[0][(size_t)b * Hh + z - 2];
        cv = g_c[(size_t)b * Hh + z - 2];
    }
    out[ZF_OFF  + i] = zv;
    out[CZF_OFF + i] = cv;
}

// ---------------------------------------------------------------------------
extern "C" void kernel_launch(void* const* d_in, const int* in_sizes, int n_in,
                              void* d_out, int out_size) {
    const float* rnn_input = (const float*)d_in[0];
    const float* tau       = (const float*)d_in[1];
    const float* z0        = (const float*)d_in[2];
    const float* c_z0      = (const float*)d_in[3];
    const float* WU_w      = (const float*)d_in[4];
    const float* WU_b      = (const float*)d_in[5];
    const float* alpha_w   = (const float*)d_in[6];
    const float* alpha_b   = (const float*)d_in[7];
    const float* Wx_w      = (const float*)d_in[8];
    const float* Wx_b      = (const float*)d_in[9];
    float* out = (float*)d_out;

    const int smem_bytes = 2 * BUFSZ + 256;   // 65792
    cudaFuncSetAttribute(gates_mma, cudaFuncAttributeMaxDynamicSharedMemorySize,
                         smem_bytes);

    repack<<<dim3(64, 16), 256>>>(WU_w);
    prep_misc<<<16, 256>>>(WU_w, WU_b);
    init_state<<<(Bb * Hh + 255) / 256, 256>>>(z0, c_z0);

    for (int t = 0; t < Tt; t++) {
        gates_mma<<<dim3(4, 64), 128, smem_bytes>>>(rnn_input, out, t);
        alpha_x<<<Bb, 128>>>(alpha_w, alpha_b, Wx_w, Wx_b,
                             rnn_input, tau, out, t);
    }
    finalize<<<(Bb * Zz + 127) / 128, 128>>>(c_z0, out);
}

// round 7
// speedup vs baseline: 5.0370x; 2.0321x over previous
#include <cuda_runtime.h>
#include <cuda_fp16.h>
#include <math.h>
#include <stdint.h>

#define Bb   256
#define Tt   256
#define Hh   1024
#define Zz   1026
#define KW   1028

#define ZF_OFF   ((long long)Bb * Tt * Zz)
#define CZF_OFF  (ZF_OFF + (long long)Bb * Zz)
#define COEF_OFF (CZF_OFF + (long long)Bb * Zz)
#define MATS_OFF (COEF_OFF + (long long)Bb * Tt * 2)

// Persistent device state
__device__ float g_h[2][Bb * Hh];     // fp32 h (for alpha_x)
__device__ float g_c[Bb * Hh];
__device__ float g_x[Bb * 2];
// fp16 pre-swizzled images:
//   weights: [nb 0..63][ch 0..15] -> 64 rows x 64 k, 128B rows, SW128  (8KB each)
__device__ __align__(128) __half g_Wimg[64 * 16 * 4096];
//   activations (ping-pong): [par][mtile 0..3][ch 0..15] -> 64 rows x 64 k (8KB each)
__device__ __align__(128) __half g_Aimg[2 * 4 * 16 * 4096];
__device__ float g_bias[4096];          // gate-interleaved bias
__device__ float g_wfront[4096 * 4];    // exact fp32 first-4 columns, interleaved

__device__ __forceinline__ float sigm(float x) { return 1.0f / (1.0f + expf(-x)); }

__device__ __forceinline__ uint32_t smem_u32(const void* p) {
    uint32_t a;
    asm("{ .reg .u64 t; cvta.to.shared.u64 t, %1; cvt.u32.u64 %0, t; }" : "=r"(a) : "l"(p));
    return a;
}

__device__ __forceinline__ void ldsm4(uint32_t* r, uint32_t addr) {
    asm volatile("ldmatrix.sync.aligned.m8n8.x4.shared.b16 {%0,%1,%2,%3}, [%4];"
                 : "=r"(r[0]), "=r"(r[1]), "=r"(r[2]), "=r"(r[3]) : "r"(addr));
}

__device__ __forceinline__ void mma16816(float (&d)[4], const uint32_t* a,
                                         uint32_t b0, uint32_t b1) {
    asm volatile(
        "mma.sync.aligned.m16n8k16.row.col.f32.f16.f16.f32 "
        "{%0,%1,%2,%3}, {%4,%5,%6,%7}, {%8,%9}, {%0,%1,%2,%3};"
        : "+f"(d[0]), "+f"(d[1]), "+f"(d[2]), "+f"(d[3])
        : "r"(a[0]), "r"(a[1]), "r"(a[2]), "r"(a[3]), "r"(b0), "r"(b1));
}

#define BUFSZ 16384     // A 8K | B 8K
#define NSTG  3
#define DSTRIDE 66

// ---------------------------------------------------------------------------
// repack: W -> gate-interleaved fp16, pre-swizzled SMEM image
// ---------------------------------------------------------------------------
__global__ void repack(const float* __restrict__ WU_w) {
    int nb = blockIdx.x, ch = blockIdx.y;
    char* base = (char*)g_Wimg + ((size_t)(nb * 16 + ch) << 13);
    for (int e = threadIdx.x; e < 4096; e += 256) {
        int r = e >> 6, c = e & 63;
        int rg = nb * 64 + r;
        int u = rg >> 2, g = rg & 3;
        float w = WU_w[(size_t)(g * Hh + u) * KW + 4 + ch * 64 + c];
        uint32_t off = (uint32_t)(r * 128 + c * 2);
        off ^= (off >> 3) & 0x70;
        *(__half*)(base + off) = __float2half_rn(w);
    }
}

__global__ void prep_misc(const float* __restrict__ WU_w,
                          const float* __restrict__ WU_b) {
    int r = blockIdx.x * 256 + threadIdx.x;
    if (r >= 4096) return;
    int u = r >> 2, g = r & 3;
    g_bias[r] = WU_b[g * Hh + u];
    const float* src = WU_w + (size_t)(g * Hh + u) * KW;
    #pragma unroll
    for (int j = 0; j < 4; j++) g_wfront[r * 4 + j] = src[j];
}

__global__ void init_state(const float* __restrict__ z0,
                           const float* __restrict__ c_z0) {
    int i = blockIdx.x * blockDim.x + threadIdx.x;
    if (i < Bb * Hh) {
        int b = i / Hh, j = i - b * Hh;
        float hv = z0[(size_t)b * Zz + 2 + j];
        g_h[0][i] = hv;
        g_c[i]    = c_z0[(size_t)b * Zz + 2 + j];
        // A image parity 0
        int mt = b >> 6, row = b & 63, ch = j >> 6, kc = j & 63;
        uint32_t rel = (uint32_t)(row * 128 + kc * 2);
        rel ^= (rel >> 3) & 0x70;
        *(__half*)((char*)g_Aimg + ((size_t)(mt * 16 + ch) << 13) + rel)
            = __float2half_rn(hv);
    }
    if (i < Bb * 2) {
        int b = i >> 1, s = i & 1;
        g_x[i] = z0[(size_t)b * Zz + s];
    }
}

// ---------------------------------------------------------------------------
// Stage one K-chunk: pure identity cp.async (A image + B image, 8KB each)
// ---------------------------------------------------------------------------
__device__ __forceinline__ void stage(uint32_t sb, int par, int mb, int nb,
                                      int tid, int ch, int buf) {
    uint32_t dst = sb + buf * BUFSZ;
    const char* asrc = (const char*)g_Aimg + ((size_t)((par * 4 + mb) * 16 + ch) << 13);
    const char* bsrc = (const char*)g_Wimg + ((size_t)(nb * 16 + ch) << 13);
    #pragma unroll
    for (int it = 0; it < 4; it++) {
        int f = (it * 128 + tid) * 16;
        asm volatile("cp.async.cg.shared.global [%0], [%1], 16;"
                     :: "r"(dst + f), "l"(asrc + f) : "memory");
    }
    #pragma unroll
    for (int it = 0; it < 4; it++) {
        int f = (it * 128 + tid) * 16;
        asm volatile("cp.async.cg.shared.global [%0], [%1], 16;"
                     :: "r"(dst + 8192 + f), "l"(bsrc + f) : "memory");
    }
}

// ---------------------------------------------------------------------------
// Gates GEMM: single-pass fp16 mma.sync + fused LSTM pointwise.
// Grid (4, 64), block 128. CTA tile: 64 batch x 64 gate-cols. 3-stage pipeline.
// ---------------------------------------------------------------------------
__global__ __launch_bounds__(128) void gates_mma(
    const float* __restrict__ rnn_input, float* __restrict__ out, int t)
{
    extern __shared__ char smraw[];
    uint32_t sb0 = smem_u32(smraw);
    uint32_t pad = (128u - (sb0 & 127u)) & 127u;
    char* smb = smraw + pad;
    uint32_t sb = sb0 + pad;

    int tid = threadIdx.x;
    int mb = blockIdx.x, nb = blockIdx.y;
    int m0 = mb * 64;
    int par = t & 1;
    float* hout = g_h[par ^ 1];

    stage(sb, par, mb, nb, tid, 0, 0);
    asm volatile("cp.async.commit_group;" ::: "memory");
    stage(sb, par, mb, nb, tid, 1, 1);
    asm volatile("cp.async.commit_group;" ::: "memory");

    float acc[8][4];
    #pragma unroll
    for (int j = 0; j < 8; j++)
        #pragma unroll
        for (int q = 0; q < 4; q++) acc[j][q] = 0.0f;

    int w = tid >> 5, lane = tid & 31;
    int arow = w * 16 + (lane & 15);
    uint32_t a_roff = (uint32_t)arow * 128;
    uint32_t a_kx   = (uint32_t)((lane >> 4) * 16);
    uint32_t a_xm   = (uint32_t)((arow & 7) << 4);
    int brow = (lane & 7) + ((lane >> 4) & 1) * 8;
    uint32_t b_kx = (uint32_t)(((lane >> 3) & 1) * 16);
    uint32_t b_xm = (uint32_t)((lane & 7) << 4);

    for (int c = 0; c < 16; c++) {
        if (c == 15) asm volatile("cp.async.wait_group 0;" ::: "memory");
        else         asm volatile("cp.async.wait_group 1;" ::: "memory");
        __syncthreads();
        if (c + 2 < 16) {
            stage(sb, par, mb, nb, tid, c + 2, (c + 2) % NSTG);
            asm volatile("cp.async.commit_group;" ::: "memory");
        }
        uint32_t ab  = sb + (uint32_t)((c % NSTG) * BUFSZ);
        uint32_t bhi = ab + 8192;
        #pragma unroll
        for (int kk = 0; kk < 4; kk++) {
            uint32_t kofs = (uint32_t)(kk * 32);
            uint32_t Ah[4];
            ldsm4(Ah, ab + a_roff + ((a_kx + kofs) ^ a_xm));
            #pragma unroll
            for (int p = 0; p < 4; p++) {
                uint32_t Bh[4];
                ldsm4(Bh, bhi + (uint32_t)((p * 16 + brow) * 128)
                              + ((b_kx + kofs) ^ b_xm));
                mma16816(acc[2*p],     Ah, Bh[0], Bh[1]);
                mma16816(acc[2*p + 1], Ah, Bh[2], Bh[3]);
            }
        }
    }
    __syncthreads();   // buffers free; reuse smem for D

    float* D = (float*)smb;
    int r0 = w * 16 + (lane >> 2);
    int c0b = (lane & 3) * 2;
    #pragma unroll
    for (int j = 0; j < 8; j++) {
        int c0 = j * 8 + c0b;
        *(float2*)&D[r0 * DSTRIDE + c0]       = make_float2(acc[j][0], acc[j][1]);
        *(float2*)&D[(r0 + 8) * DSTRIDE + c0] = make_float2(acc[j][2], acc[j][3]);
    }
    __syncthreads();

    // Pointwise: thread -> (row = tid>>1, 8 units)
    int row = tid >> 1;
    int ub  = (tid & 1) * 8;
    int b   = m0 + row;
    float xp0 = g_x[b * 2], xp1 = g_x[b * 2 + 1];
    const float* ibp = rnn_input + (size_t)b * Tt * 2 + (size_t)t * 2;
    float in0 = ibp[0], in1 = ibp[1];

    float* cptr = g_c + (size_t)b * Hh + nb * 16 + ub;
    float* hp   = hout + (size_t)b * Hh + nb * 16 + ub;
    float* op   = out + (size_t)b * Tt * Zz + (size_t)t * Zz + 2 + nb * 16 + ub;

    float cc[8], hnv[8];
    #pragma unroll
    for (int q = 0; q < 2; q++) {
        float4 v = *(float4*)(cptr + q * 4);
        cc[4*q] = v.x; cc[4*q+1] = v.y; cc[4*q+2] = v.z; cc[4*q+3] = v.w;
    }
    #pragma unroll
    for (int q = 0; q < 8; q++) {
        int ul = ub + q;
        int rg = nb * 64 + ul * 4;
        float4 bias = *(const float4*)(g_bias + rg);
        float bv[4] = {bias.x, bias.y, bias.z, bias.w};
        float gv[4];
        #pragma unroll
        for (int g2 = 0; g2 < 4; g2++) {
            float4 wf = *(const float4*)(g_wfront + (size_t)(rg + g2) * 4);
            gv[g2] = D[row * DSTRIDE + ul * 4 + g2] + bv[g2]
                   + xp0 * wf.x + xp1 * wf.y + in0 * wf.z + in1 * wf.w;
        }
        float ig = sigm(gv[0]), fg = sigm(gv[1]);
        float gg = tanhf(gv[2]), og = sigm(gv[3]);
        float cn = fg * cc[q] + ig * gg;
        cc[q] = cn;
        hnv[q] = og * tanhf(cn);
    }
    #pragma unroll
    for (int q = 0; q < 2; q++) {
        *(float4*)(cptr + q * 4) = make_float4(cc[4*q], cc[4*q+1], cc[4*q+2], cc[4*q+3]);
        *(float4*)(hp + q * 4)   = make_float4(hnv[4*q], hnv[4*q+1], hnv[4*q+2], hnv[4*q+3]);
    }
    // out row only 8-byte aligned (Zz = 1026) -> float2 stores
    #pragma unroll
    for (int q = 0; q < 4; q++)
        *(float2*)(op + q * 2) = make_float2(hnv[2*q], hnv[2*q+1]);

    // Write next-step A image (fp16, pre-swizzled): 16B per thread
    {
        int ch = nb >> 2;
        int kc = (nb & 3) * 16 + ub;
        uint32_t rel = (uint32_t)(row * 128) + (((uint32_t)(kc * 2)) ^ ((row & 7) << 4));
        __half2 hx[4];
        #pragma unroll
        for (int j = 0; j < 4; j++)
            hx[j] = __floats2half2_rn(hnv[2*j], hnv[2*j+1]);
        char* idst = (char*)g_Aimg
                   + ((size_t)(((par ^ 1) * 4 + mb) * 16 + ch) << 13) + rel;
        *(uint4*)idst = *(uint4*)hx;
    }
}

// ---------------------------------------------------------------------------
__global__ __launch_bounds__(128) void alpha_x(
    const float* __restrict__ alpha_w, const float* __restrict__ alpha_b,
    const float* __restrict__ Wx_w,    const float* __restrict__ Wx_b,
    const float* __restrict__ rnn_input, const float* __restrict__ tau,
    float* __restrict__ out, int t)
{
    int b = blockIdx.x, tid = threadIdx.x;
    const float* __restrict__ h = g_h[(t & 1) ^ 1] + (size_t)b * Hh;
    float s0 = 0.f, s1 = 0.f, s2 = 0.f, s3 = 0.f;
    for (int k = tid; k < Hh; k += 128) {
        float hv = h[k];
        s0 = fmaf(hv, alpha_w[k],      s0);
        s1 = fmaf(hv, alpha_w[Hh + k], s1);
        s2 = fmaf(hv, Wx_w[k],         s2);
        s3 = fmaf(hv, Wx_w[Hh + k],    s3);
    }
    #pragma unroll
    for (int off = 16; off > 0; off >>= 1) {
        s0 += __shfl_down_sync(0xffffffffu, s0, off);
        s1 += __shfl_down_sync(0xffffffffu, s1, off);
        s2 += __shfl_down_sync(0xffffffffu, s2, off);
        s3 += __shfl_down_sync(0xffffffffu, s3, off);
    }
    __shared__ float red[4][4];
    if ((tid & 31) == 0) {
        int w = tid >> 5;
        red[w][0] = s0; red[w][1] = s1; red[w][2] = s2; red[w][3] = s3;
    }
    __syncthreads();
    if (tid == 0) {
        s0 = red[0][0] + red[1][0] + red[2][0] + red[3][0];
        s1 = red[0][1] + red[1][1] + red[2][1] + red[3][1];
        s2 = red[0][2] + red[1][2] + red[2][2] + red[3][2];
        s3 = red[0][3] + red[1][3] + red[2][3] + red[3][3];

        float x1 = g_x[b * 2 + 0], x2 = g_x[b * 2 + 1];
        float u  = rnn_input[(size_t)b * Tt * 2 + (size_t)t * 2];
        float ta = tau[(size_t)b * Tt + t];
        float a10 = -1.0f - 2.0f * x1 * x2;
        float a11 = 1.0f - x1 * x1;
        float xm0 = x1 + ta * x2;
        float xm1 = x2 + ta * (a10 * x1 + a11 * x2 + u);
        float al0 = sigm(s0 + alpha_b[0]);
        float al1 = sigm(s1 + alpha_b[1]);
        float xn0 = (1.0f - al0) * xm0 + al0 * (s2 + Wx_b[0]);
        float xn1 = (1.0f - al1) * xm1 + al1 * (s3 + Wx_b[1]);
        g_x[b * 2 + 0] = xn0;
        g_x[b * 2 + 1] = xn1;

        size_t ob = (size_t)b * Tt * Zz + (size_t)t * Zz;
        out[ob + 0] = xn0;
        out[ob + 1] = xn1;
        size_t cb = COEF_OFF + (size_t)b * Tt * 2 + (size_t)t * 2;
        out[cb + 0] = al0;
        out[cb + 1] = al1;
        if (b == 0) {
            size_t mb2 = MATS_OFF + (size_t)t * 4;
            out[mb2 + 0] = 0.0f;
            out[mb2 + 1] = 1.0f;
            out[mb2 + 2] = a10;
            out[mb2 + 3] = a11;
        }
    }
}

__global__ void finalize(const float* __restrict__ c_z0,
                         float* __restrict__ out) {
    int i = blockIdx.x * blockDim.x + threadIdx.x;
    if (i >= Bb * Zz) return;
    int b = i / Zz, z = i - b * Zz;
    float zv, cv;
    if (z < 2) {
        zv = g_x[b * 2 + z];
        cv = c_z0[(size_t)b * Zz + z];
    } else {
        zv = g_h[0][(size_t)b * Hh + z - 2];
        cv = g_c[(size_t)b * Hh + z - 2];
    }
    out[ZF_OFF  + i] = zv;
    out[CZF_OFF + i] = cv;
}

// ---------------------------------------------------------------------------
extern "C" void kernel_launch(void* const* d_in, const int* in_sizes, int n_in,
                              void* d_out, int out_size) {
    const float* rnn_input = (const float*)d_in[0];
    const float* tau       = (const float*)d_in[1];
    const float* z0        = (const float*)d_in[2];
    const float* c_z0      = (const float*)d_in[3];
    const float* WU_w      = (const float*)d_in[4];
    const float* WU_b      = (const float*)d_in[5];
    const float* alpha_w   = (const float*)d_in[6];
    const float* alpha_b   = (const float*)d_in[7];
    const float* Wx_w      = (const float*)d_in[8];
    const float* Wx_b      = (const float*)d_in[9];
    float* out = (float*)d_out;

    const int smem_bytes = NSTG * BUFSZ + 256;   // 49408
    cudaFuncSetAttribute(gates_mma, cudaFuncAttributeMaxDynamicSharedMemorySize,
                         smem_bytes);

    repack<<<dim3(64, 16), 256>>>(WU_w);
    prep_misc<<<16, 256>>>(WU_w, WU_b);
    init_state<<<(Bb * Hh + 255) / 256, 256>>>(z0, c_z0);

    for (int t = 0; t < Tt; t++) {
        gates_mma<<<dim3(4, 64), 128, smem_bytes>>>(rnn_input, out, t);
        alpha_x<<<Bb, 128>>>(alpha_w, alpha_b, Wx_w, Wx_b,
                             rnn_input, tau, out, t);
    }
    finalize<<<(Bb * Zz + 127) / 128, 128>>>(c_z0, out);
}

// round 8
// speedup vs baseline: 5.3342x; 1.0590x over previous
#include <cuda_runtime.h>
#include <cuda_fp16.h>
#include <math.h>
#include <stdint.h>

#define Bb   256
#define Tt   256
#define Hh   1024
#define Zz   1026
#define KW   1028

#define ZF_OFF   ((long long)Bb * Tt * Zz)
#define CZF_OFF  (ZF_OFF + (long long)Bb * Zz)
#define COEF_OFF (CZF_OFF + (long long)Bb * Zz)
#define MATS_OFF (COEF_OFF + (long long)Bb * Tt * 2)

// Persistent device state
__device__ float g_h[2][Bb * Hh];     // fp32 h (for alpha_x)
__device__ float g_c[Bb * Hh];
__device__ float g_x[Bb * 2];
// fp16 pre-swizzled images (8KB blocks of 64 rows x 64 k, 128B rows, SW128):
__device__ __align__(128) __half g_Wimg[64 * 16 * 4096];          // [nb][ch]
__device__ __align__(128) __half g_Aimg[2 * 4 * 16 * 4096];       // [par][mt][ch]
__device__ float g_bias[4096];          // gate-interleaved bias
__device__ float g_wfront[4096 * 4];    // exact fp32 first-4 columns, interleaved

__device__ __forceinline__ float sigm(float x) { return 1.0f / (1.0f + expf(-x)); }

__device__ __forceinline__ uint32_t smem_u32(const void* p) {
    uint32_t a;
    asm("{ .reg .u64 t; cvta.to.shared.u64 t, %1; cvt.u32.u64 %0, t; }" : "=r"(a) : "l"(p));
    return a;
}

__device__ __forceinline__ void ldsm4(uint32_t* r, uint32_t addr) {
    asm volatile("ldmatrix.sync.aligned.m8n8.x4.shared.b16 {%0,%1,%2,%3}, [%4];"
                 : "=r"(r[0]), "=r"(r[1]), "=r"(r[2]), "=r"(r[3]) : "r"(addr));
}

__device__ __forceinline__ void mma16816(float (&d)[4], const uint32_t* a,
                                         uint32_t b0, uint32_t b1) {
    asm volatile(
        "mma.sync.aligned.m16n8k16.row.col.f32.f16.f16.f32 "
        "{%0,%1,%2,%3}, {%4,%5,%6,%7}, {%8,%9}, {%0,%1,%2,%3};"
        : "+f"(d[0]), "+f"(d[1]), "+f"(d[2]), "+f"(d[3])
        : "r"(a[0]), "r"(a[1]), "r"(a[2]), "r"(a[3]), "r"(b0), "r"(b1));
}

// Stage layout (48KB): A[k0][mt0] A[k0][mt1] A[k1][mt0] A[k1][mt1] B[k0] B[k1]
#define BUFSZ 49152
#define NSTG  3
#define NCHUNK 8
#define DSTRIDE 66

// ---------------------------------------------------------------------------
__global__ void repack(const float* __restrict__ WU_w) {
    int nb = blockIdx.x, ch = blockIdx.y;
    char* base = (char*)g_Wimg + ((size_t)(nb * 16 + ch) << 13);
    for (int e = threadIdx.x; e < 4096; e += 256) {
        int r = e >> 6, c = e & 63;
        int rg = nb * 64 + r;
        int u = rg >> 2, g = rg & 3;
        float w = WU_w[(size_t)(g * Hh + u) * KW + 4 + ch * 64 + c];
        uint32_t off = (uint32_t)(r * 128 + c * 2);
        off ^= (off >> 3) & 0x70;
        *(__half*)(base + off) = __float2half_rn(w);
    }
}

__global__ void prep_misc(const float* __restrict__ WU_w,
                          const float* __restrict__ WU_b) {
    int r = blockIdx.x * 256 + threadIdx.x;
    if (r >= 4096) return;
    int u = r >> 2, g = r & 3;
    g_bias[r] = WU_b[g * Hh + u];
    const float* src = WU_w + (size_t)(g * Hh + u) * KW;
    #pragma unroll
    for (int j = 0; j < 4; j++) g_wfront[r * 4 + j] = src[j];
}

__global__ void init_state(const float* __restrict__ z0,
                           const float* __restrict__ c_z0) {
    int i = blockIdx.x * blockDim.x + threadIdx.x;
    if (i < Bb * Hh) {
        int b = i / Hh, j = i - b * Hh;
        float hv = z0[(size_t)b * Zz + 2 + j];
        g_h[0][i] = hv;
        g_c[i]    = c_z0[(size_t)b * Zz + 2 + j];
        int mt = b >> 6, row = b & 63, ch = j >> 6, kc = j & 63;
        uint32_t rel = (uint32_t)(row * 128 + kc * 2);
        rel ^= (rel >> 3) & 0x70;
        *(__half*)((char*)g_Aimg + ((size_t)(mt * 16 + ch) << 13) + rel)
            = __float2half_rn(hv);
    }
    if (i < Bb * 2) {
        int b = i >> 1, s = i & 1;
        g_x[i] = z0[(size_t)b * Zz + s];
    }
}

// ---------------------------------------------------------------------------
// Stage one K-128 chunk: 4 A blocks (2 k-sub x 2 m-sub) + 2 B blocks, identity
// ---------------------------------------------------------------------------
__device__ __forceinline__ void stage(uint32_t sb, int par, int mb, int nb,
                                      int tid, int ch2, int buf) {
    uint32_t dst = sb + buf * BUFSZ;
    int ch0 = ch2 * 2;
    const char* abase = (const char*)g_Aimg + ((size_t)(par * 4 + mb * 2) * 16 << 13);
    const char* bbase = (const char*)g_Wimg + ((size_t)(nb * 16) << 13);
    // A: blocks [kblk][mtblk] -> src block (mb*2+mtblk)*16 + ch0+kblk
    #pragma unroll
    for (int blk = 0; blk < 4; blk++) {
        int kblk = blk >> 1, mtblk = blk & 1;
        const char* src = abase + (((size_t)(mtblk * 16 + ch0 + kblk)) << 13);
        uint32_t d = dst + (uint32_t)(blk ^ ((blk >> 1) ^ (blk & 1) ? 0 : 0)) * 0; // no-op
        d = dst + (uint32_t)((kblk * 2 + mtblk) << 13);
        #pragma unroll
        for (int it = 0; it < 2; it++) {
            int f = (it * 256 + tid) * 16;
            asm volatile("cp.async.cg.shared.global [%0], [%1], 16;"
                         :: "r"(d + f), "l"(src + f) : "memory");
        }
    }
    // B: 2 blocks
    #pragma unroll
    for (int kblk = 0; kblk < 2; kblk++) {
        const char* src = bbase + (((size_t)(ch0 + kblk)) << 13);
        uint32_t d = dst + 32768 + (uint32_t)(kblk << 13);
        #pragma unroll
        for (int it = 0; it < 2; it++) {
            int f = (it * 256 + tid) * 16;
            asm volatile("cp.async.cg.shared.global [%0], [%1], 16;"
                         :: "r"(d + f), "l"(src + f) : "memory");
        }
    }
}

// ---------------------------------------------------------------------------
// Gates GEMM: fp16 mma.sync, CTA tile 128x64, 8 warps, 3-stage K-128 pipeline
// Grid (2, 64), block 256.
// ---------------------------------------------------------------------------
__global__ __launch_bounds__(256) void gates_mma(
    const float* __restrict__ rnn_input, float* __restrict__ out, int t)
{
    extern __shared__ char smraw[];
    uint32_t sb0 = smem_u32(smraw);
    uint32_t pad = (128u - (sb0 & 127u)) & 127u;
    char* smb = smraw + pad;
    uint32_t sb = sb0 + pad;

    int tid = threadIdx.x;
    int mb = blockIdx.x, nb = blockIdx.y;
    int m0 = mb * 128;
    int par = t & 1;
    float* hout = g_h[par ^ 1];

    stage(sb, par, mb, nb, tid, 0, 0);
    asm volatile("cp.async.commit_group;" ::: "memory");
    stage(sb, par, mb, nb, tid, 1, 1);
    asm volatile("cp.async.commit_group;" ::: "memory");

    float acc[8][4];
    #pragma unroll
    for (int j = 0; j < 8; j++)
        #pragma unroll
        for (int q = 0; q < 4; q++) acc[j][q] = 0.0f;

    int w = tid >> 5, lane = tid & 31;
    int mtblk = w >> 2;                     // 0..1: which 64-row A block
    int r64   = (w & 3) * 16 + (lane & 15); // row within A block
    uint32_t a_boff = (uint32_t)(mtblk << 13) + (uint32_t)r64 * 128;
    uint32_t a_kx   = (uint32_t)((lane >> 4) * 16);
    uint32_t a_xm   = (uint32_t)((r64 & 7) << 4);
    int brow = (lane & 7) + ((lane >> 4) & 1) * 8;
    uint32_t b_kx = (uint32_t)(((lane >> 3) & 1) * 16);
    uint32_t b_xm = (uint32_t)((lane & 7) << 4);

    for (int c = 0; c < NCHUNK; c++) {
        if (c == NCHUNK - 1) asm volatile("cp.async.wait_group 0;" ::: "memory");
        else                 asm volatile("cp.async.wait_group 1;" ::: "memory");
        __syncthreads();
        if (c + 2 < NCHUNK) {
            stage(sb, par, mb, nb, tid, c + 2, (c + 2) % NSTG);
            asm volatile("cp.async.commit_group;" ::: "memory");
        }
        uint32_t ab = sb + (uint32_t)((c % NSTG) * BUFSZ);
        #pragma unroll
        for (int kblk = 0; kblk < 2; kblk++) {
            uint32_t abase = ab + (uint32_t)(kblk << 14) + a_boff;
            uint32_t bbase = ab + 32768 + (uint32_t)(kblk << 13);
            #pragma unroll
            for (int kk = 0; kk < 4; kk++) {
                uint32_t kofs = (uint32_t)(kk * 32);
                uint32_t Ah[4];
                ldsm4(Ah, abase + ((a_kx + kofs) ^ a_xm));
                #pragma unroll
                for (int p = 0; p < 4; p++) {
                    uint32_t Bh[4];
                    ldsm4(Bh, bbase + (uint32_t)((p * 16 + brow) * 128)
                                    + ((b_kx + kofs) ^ b_xm));
                    mma16816(acc[2*p],     Ah, Bh[0], Bh[1]);
                    mma16816(acc[2*p + 1], Ah, Bh[2], Bh[3]);
                }
            }
        }
    }
    __syncthreads();   // buffers free; reuse smem for D (128 x 66 floats)

    float* D = (float*)smb;
    int r0 = w * 16 + (lane >> 2);
    int c0b = (lane & 3) * 2;
    #pragma unroll
    for (int j = 0; j < 8; j++) {
        int c0 = j * 8 + c0b;
        *(float2*)&D[r0 * DSTRIDE + c0]       = make_float2(acc[j][0], acc[j][1]);
        *(float2*)&D[(r0 + 8) * DSTRIDE + c0] = make_float2(acc[j][2], acc[j][3]);
    }
    __syncthreads();

    // Pointwise: thread -> (row = tid>>1 of 128, 8 units)
    int row = tid >> 1;
    int ub  = (tid & 1) * 8;
    int b   = m0 + row;
    float xp0 = g_x[b * 2], xp1 = g_x[b * 2 + 1];
    const float* ibp = rnn_input + (size_t)b * Tt * 2 + (size_t)t * 2;
    float in0 = ibp[0], in1 = ibp[1];

    float* cptr = g_c + (size_t)b * Hh + nb * 16 + ub;
    float* hp   = hout + (size_t)b * Hh + nb * 16 + ub;
    float* op   = out + (size_t)b * Tt * Zz + (size_t)t * Zz + 2 + nb * 16 + ub;

    float cc[8], hnv[8];
    #pragma unroll
    for (int q = 0; q < 2; q++) {
        float4 v = *(float4*)(cptr + q * 4);
        cc[4*q] = v.x; cc[4*q+1] = v.y; cc[4*q+2] = v.z; cc[4*q+3] = v.w;
    }
    #pragma unroll
    for (int q = 0; q < 8; q++) {
        int ul = ub + q;
        int rg = nb * 64 + ul * 4;
        float4 bias = *(const float4*)(g_bias + rg);
        float bv[4] = {bias.x, bias.y, bias.z, bias.w};
        float gv[4];
        #pragma unroll
        for (int g2 = 0; g2 < 4; g2++) {
            float4 wf = *(const float4*)(g_wfront + (size_t)(rg + g2) * 4);
            gv[g2] = D[row * DSTRIDE + ul * 4 + g2] + bv[g2]
                   + xp0 * wf.x + xp1 * wf.y + in0 * wf.z + in1 * wf.w;
        }
        float ig = sigm(gv[0]), fg = sigm(gv[1]);
        float gg = tanhf(gv[2]), og = sigm(gv[3]);
        float cn = fg * cc[q] + ig * gg;
        cc[q] = cn;
        hnv[q] = og * tanhf(cn);
    }
    #pragma unroll
    for (int q = 0; q < 2; q++) {
        *(float4*)(cptr + q * 4) = make_float4(cc[4*q], cc[4*q+1], cc[4*q+2], cc[4*q+3]);
        *(float4*)(hp + q * 4)   = make_float4(hnv[4*q], hnv[4*q+1], hnv[4*q+2], hnv[4*q+3]);
    }
    // out row only 8-byte aligned (Zz = 1026) -> float2 stores
    #pragma unroll
    for (int q = 0; q < 4; q++)
        *(float2*)(op + q * 2) = make_float2(hnv[2*q], hnv[2*q+1]);

    // Write next-step A image (fp16, pre-swizzled): 16B per thread
    {
        int mt = b >> 6, row64 = b & 63;
        int ch = nb >> 2;
        int kc = (nb & 3) * 16 + ub;
        uint32_t rel = (uint32_t)(row64 * 128)
                     + (((uint32_t)(kc * 2)) ^ ((row64 & 7) << 4));
        __half2 hx[4];
        #pragma unroll
        for (int j = 0; j < 4; j++)
            hx[j] = __floats2half2_rn(hnv[2*j], hnv[2*j+1]);
        char* idst = (char*)g_Aimg
                   + ((size_t)(((par ^ 1) * 4 + mt) * 16 + ch) << 13) + rel;
        *(uint4*)idst = *(uint4*)hx;
    }
}

// ---------------------------------------------------------------------------
__global__ __launch_bounds__(128) void alpha_x(
    const float* __restrict__ alpha_w, const float* __restrict__ alpha_b,
    const float* __restrict__ Wx_w,    const float* __restrict__ Wx_b,
    const float* __restrict__ rnn_input, const float* __restrict__ tau,
    float* __restrict__ out, int t)
{
    int b = blockIdx.x, tid = threadIdx.x;
    const float* __restrict__ h = g_h[(t & 1) ^ 1] + (size_t)b * Hh;
    float s0 = 0.f, s1 = 0.f, s2 = 0.f, s3 = 0.f;
    for (int k = tid; k < Hh; k += 128) {
        float hv = h[k];
        s0 = fmaf(hv, alpha_w[k],      s0);
        s1 = fmaf(hv, alpha_w[Hh + k], s1);
        s2 = fmaf(hv, Wx_w[k],         s2);
        s3 = fmaf(hv, Wx_w[Hh + k],    s3);
    }
    #pragma unroll
    for (int off = 16; off > 0; off >>= 1) {
        s0 += __shfl_down_sync(0xffffffffu, s0, off);
        s1 += __shfl_down_sync(0xffffffffu, s1, off);
        s2 += __shfl_down_sync(0xffffffffu, s2, off);
        s3 += __shfl_down_sync(0xffffffffu, s3, off);
    }
    __shared__ float red[4][4];
    if ((tid & 31) == 0) {
        int w = tid >> 5;
        red[w][0] = s0; red[w][1] = s1; red[w][2] = s2; red[w][3] = s3;
    }
    __syncthreads();
    if (tid == 0) {
        s0 = red[0][0] + red[1][0] + red[2][0] + red[3][0];
        s1 = red[0][1] + red[1][1] + red[2][1] + red[3][1];
        s2 = red[0][2] + red[1][2] + red[2][2] + red[3][2];
        s3 = red[0][3] + red[1][3] + red[2][3] + red[3][3];

        float x1 = g_x[b * 2 + 0], x2 = g_x[b * 2 + 1];
        float u  = rnn_input[(size_t)b * Tt * 2 + (size_t)t * 2];
        float ta = tau[(size_t)b * Tt + t];
        float a10 = -1.0f - 2.0f * x1 * x2;
        float a11 = 1.0f - x1 * x1;
        float xm0 = x1 + ta * x2;
        float xm1 = x2 + ta * (a10 * x1 + a11 * x2 + u);
        float al0 = sigm(s0 + alpha_b[0]);
        float al1 = sigm(s1 + alpha_b[1]);
        float xn0 = (1.0f - al0) * xm0 + al0 * (s2 + Wx_b[0]);
        float xn1 = (1.0f - al1) * xm1 + al1 * (s3 + Wx_b[1]);
        g_x[b * 2 + 0] = xn0;
        g_x[b * 2 + 1] = xn1;

        size_t ob = (size_t)b * Tt * Zz + (size_t)t * Zz;
        out[ob + 0] = xn0;
        out[ob + 1] = xn1;
        size_t cb = COEF_OFF + (size_t)b * Tt * 2 + (size_t)t * 2;
        out[cb + 0] = al0;
        out[cb + 1] = al1;
        if (b == 0) {
            size_t mb2 = MATS_OFF + (size_t)t * 4;
            out[mb2 + 0] = 0.0f;
            out[mb2 + 1] = 1.0f;
            out[mb2 + 2] = a10;
            out[mb2 + 3] = a11;
        }
    }
}

__global__ void finalize(const float* __restrict__ c_z0,
                         float* __restrict__ out) {
    int i = blockIdx.x * blockDim.x + threadIdx.x;
    if (i >= Bb * Zz) return;
    int b = i / Zz, z = i - b * Zz;
    float zv, cv;
    if (z < 2) {
        zv = g_x[b * 2 + z];
        cv = c_z0[(size_t)b * Zz + z];
    } else {
        zv = g_h[0][(size_t)b * Hh + z - 2];
        cv = g_c[(size_t)b * Hh + z - 2];
    }
    out[ZF_OFF  + i] = zv;
    out[CZF_OFF + i] = cv;
}

// ---------------------------------------------------------------------------
extern "C" void kernel_launch(void* const* d_in, const int* in_sizes, int n_in,
                              void* d_out, int out_size) {
    const float* rnn_input = (const float*)d_in[0];
    const float* tau       = (const float*)d_in[1];
    const float* z0        = (const float*)d_in[2];
    const float* c_z0      = (const float*)d_in[3];
    const float* WU_w      = (const float*)d_in[4];
    const float* WU_b      = (const float*)d_in[5];
    const float* alpha_w   = (const float*)d_in[6];
    const float* alpha_b   = (const float*)d_in[7];
    const float* Wx_w      = (const float*)d_in[8];
    const float* Wx_b      = (const float*)d_in[9];
    float* out = (float*)d_out;

    const int smem_bytes = NSTG * BUFSZ + 256;   // 147712
    cudaFuncSetAttribute(gates_mma, cudaFuncAttributeMaxDynamicSharedMemorySize,
                         smem_bytes);

    repack<<<dim3(64, 16), 256>>>(WU_w);
    prep_misc<<<16, 256>>>(WU_w, WU_b);
    init_state<<<(Bb * Hh + 255) / 256, 256>>>(z0, c_z0);

    for (int t = 0; t < Tt; t++) {
        gates_mma<<<dim3(2, 64), 256, smem_bytes>>>(rnn_input, out, t);
        alpha_x<<<Bb, 128>>>(alpha_w, alpha_b, Wx_w, Wx_b,
                             rnn_input, tau, out, t);
    }
    finalize<<<(Bb * Zz + 127) / 128, 128>>>(c_z0, out);
}

// round 9
// speedup vs baseline: 5.7401x; 1.0761x over previous
#include <cuda_runtime.h>
#include <cuda_fp16.h>
#include <math.h>
#include <stdint.h>

#define Bb   256
#define Tt   256
#define Hh   1024
#define Zz   1026
#define KW   1028

#define ZF_OFF   ((long long)Bb * Tt * Zz)
#define CZF_OFF  (ZF_OFF + (long long)Bb * Zz)
#define COEF_OFF (CZF_OFF + (long long)Bb * Zz)
#define MATS_OFF (COEF_OFF + (long long)Bb * Tt * 2)

// Persistent device state
__device__ float g_h[2][Bb * Hh];     // fp32 h (for alpha)
__device__ float g_c[Bb * Hh];
__device__ float g_x[Bb * 2];
// fp16 pre-swizzled images (8KB blocks: 64 rows x 64 k, 128B rows, SW128):
__device__ __align__(128) __half g_Wimg[64 * 16 * 4096];       // [nb][ch]
__device__ __align__(128) __half g_Aimg[2 * 4 * 16 * 4096];    // [par][mt][ch]
__device__ float g_bias[4096];
__device__ float g_wfront[4096 * 4];
// persistent-kernel sync state
__device__ unsigned g_bar_arrive;
__device__ unsigned g_bar_epoch;
__device__ unsigned g_xdone;

__device__ __forceinline__ float sigm(float x) { return 1.0f / (1.0f + expf(-x)); }

__device__ __forceinline__ uint32_t smem_u32(const void* p) {
    uint32_t a;
    asm("{ .reg .u64 t; cvta.to.shared.u64 t, %1; cvt.u32.u64 %0, t; }" : "=r"(a) : "l"(p));
    return a;
}

__device__ __forceinline__ void ldsm4(uint32_t* r, uint32_t addr) {
    asm volatile("ldmatrix.sync.aligned.m8n8.x4.shared.b16 {%0,%1,%2,%3}, [%4];"
                 : "=r"(r[0]), "=r"(r[1]), "=r"(r[2]), "=r"(r[3]) : "r"(addr));
}

__device__ __forceinline__ void mma16816(float (&d)[4], const uint32_t* a,
                                         uint32_t b0, uint32_t b1) {
    asm volatile(
        "mma.sync.aligned.m16n8k16.row.col.f32.f16.f16.f32 "
        "{%0,%1,%2,%3}, {%4,%5,%6,%7}, {%8,%9}, {%0,%1,%2,%3};"
        : "+f"(d[0]), "+f"(d[1]), "+f"(d[2]), "+f"(d[3])
        : "r"(a[0]), "r"(a[1]), "r"(a[2]), "r"(a[3]), "r"(b0), "r"(b1));
}

#define CPA(dst, src) \
    asm volatile("cp.async.cg.shared.global [%0], [%1], 16;" \
                 :: "r"(dst), "l"(src) : "memory")
#define CPA_COMMIT() asm volatile("cp.async.commit_group;" ::: "memory")
#define CPA_WAIT0()  asm volatile("cp.async.wait_group 0;" ::: "memory")
#define CPA_WAIT1()  asm volatile("cp.async.wait_group 1;" ::: "memory")

// SMEM layout (relative to 1024-aligned base)
#define SM_B   0        // 131072 bytes: 16 B-blocks resident
#define SM_A   131072   // 49152 bytes: 3-stage A buffers (16KB each)
#define SM_AW  180224   // 16384 bytes: alpha_w (8KB) | Wx_w (8KB)
#define SM_TOT 196608
#define DSTRIDE 66

// ---------------------------------------------------------------------------
__global__ void repack(const float* __restrict__ WU_w) {
    int nb = blockIdx.x, ch = blockIdx.y;
    char* base = (char*)g_Wimg + ((size_t)(nb * 16 + ch) << 13);
    for (int e = threadIdx.x; e < 4096; e += 256) {
        int r = e >> 6, c = e & 63;
        int rg = nb * 64 + r;
        int u = rg >> 2, g = rg & 3;
        float w = WU_w[(size_t)(g * Hh + u) * KW + 4 + ch * 64 + c];
        uint32_t off = (uint32_t)(r * 128 + c * 2);
        off ^= (off >> 3) & 0x70;
        *(__half*)(base + off) = __float2half_rn(w);
    }
}

__global__ void prep_misc(const float* __restrict__ WU_w,
                          const float* __restrict__ WU_b) {
    int r = blockIdx.x * 256 + threadIdx.x;
    if (r >= 4096) return;
    int u = r >> 2, g = r & 3;
    g_bias[r] = WU_b[g * Hh + u];
    const float* src = WU_w + (size_t)(g * Hh + u) * KW;
    #pragma unroll
    for (int j = 0; j < 4; j++) g_wfront[r * 4 + j] = src[j];
}

__global__ void init_state(const float* __restrict__ z0,
                           const float* __restrict__ c_z0) {
    int i = blockIdx.x * blockDim.x + threadIdx.x;
    if (i == 0) { g_bar_arrive = 0u; g_bar_epoch = 0u; g_xdone = 0u; }
    if (i < Bb * Hh) {
        int b = i / Hh, j = i - b * Hh;
        float hv = z0[(size_t)b * Zz + 2 + j];
        g_h[0][i] = hv;
        g_c[i]    = c_z0[(size_t)b * Zz + 2 + j];
        int mt = b >> 6, row = b & 63, ch = j >> 6, kc = j & 63;
        uint32_t rel = (uint32_t)(row * 128 + kc * 2);
        rel ^= (rel >> 3) & 0x70;
        *(__half*)((char*)g_Aimg + ((size_t)(mt * 16 + ch) << 13) + rel)
            = __float2half_rn(hv);
    }
    if (i < Bb * 2) {
        int b = i >> 1, s = i & 1;
        g_x[i] = z0[(size_t)b * Zz + s];
    }
}

// ---------------------------------------------------------------------------
// Persistent kernel: grid 128 (mb = cta&1, nb = cta>>1), block 256, 1 CTA/SM
// ---------------------------------------------------------------------------
__global__ __launch_bounds__(256) void lstm_persist(
    const float* __restrict__ rnn_input, const float* __restrict__ tau,
    const float* __restrict__ alpha_w,   const float* __restrict__ alpha_b,
    const float* __restrict__ Wx_w,      const float* __restrict__ Wx_b,
    float* __restrict__ out)
{
    extern __shared__ char smraw[];
    uint32_t sb0 = smem_u32(smraw);
    uint32_t pad = (1024u - (sb0 & 1023u)) & 1023u;
    char* smb = smraw + pad;
    uint32_t sb = sb0 + pad;
    __shared__ float red[8][4];

    int tid = threadIdx.x;
    int cta = blockIdx.x;
    int mb = cta & 1, nb = cta >> 1;
    int m0 = mb * 128;

    int w = tid >> 5, lane = tid & 31;
    int mtblk = w >> 2;
    int r64   = (w & 3) * 16 + (lane & 15);
    uint32_t a_boff = (uint32_t)(mtblk << 13) + (uint32_t)r64 * 128;
    uint32_t a_kx   = (uint32_t)((lane >> 4) * 16);
    uint32_t a_xm   = (uint32_t)((r64 & 7) << 4);
    int brow = (lane & 7) + ((lane >> 4) & 1) * 8;
    uint32_t b_kx = (uint32_t)(((lane >> 3) & 1) * 16);
    uint32_t b_xm = (uint32_t)((lane & 7) << 4);

    // ---- prologue: resident B (128KB) + alpha/Wx weights (16KB) ----
    {
        const char* bsrc = (const char*)g_Wimg + ((size_t)(nb * 16) << 13);
        #pragma unroll
        for (int it = 0; it < 32; it++) {
            uint32_t f = (uint32_t)((it * 256 + tid) * 16);
            CPA(sb + SM_B + f, bsrc + f);
        }
        #pragma unroll
        for (int it = 0; it < 2; it++) {
            uint32_t f = (uint32_t)((it * 256 + tid) * 16);
            CPA(sb + SM_AW + f, (const char*)alpha_w + f);
            CPA(sb + SM_AW + 8192 + f, (const char*)Wx_w + f);
        }
        CPA_COMMIT();
        CPA_WAIT0();
        __syncthreads();
    }
    float ab0 = alpha_b[0], ab1 = alpha_b[1];
    float wb0 = Wx_b[0],    wb1 = Wx_b[1];

    for (int t = 0; t < Tt; t++) {
        int par = t & 1;
        float* hout = g_h[par ^ 1];
        const char* agbase = (const char*)g_Aimg
                           + ((size_t)((par * 4 + mb * 2) * 16) << 13);

        // stage chunk c into buf: A only (two 8KB blocks: mt0, mt1)
        #define STAGE_A(c_, buf_) do {                                        \
            uint32_t dst_ = sb + SM_A + (uint32_t)((buf_) * 16384);           \
            _Pragma("unroll")                                                 \
            for (int mt_ = 0; mt_ < 2; mt_++) {                               \
                const char* src_ = agbase + (((size_t)(mt_ * 16 + (c_))) << 13);\
                _Pragma("unroll")                                             \
                for (int it_ = 0; it_ < 2; it_++) {                           \
                    uint32_t f_ = (uint32_t)((it_ * 256 + tid) * 16);         \
                    CPA(dst_ + (uint32_t)(mt_ << 13) + f_, src_ + f_);        \
                }                                                             \
            }                                                                 \
        } while (0)

        STAGE_A(0, 0); CPA_COMMIT();
        STAGE_A(1, 1); CPA_COMMIT();

        float acc[8][4];
        #pragma unroll
        for (int j = 0; j < 8; j++)
            #pragma unroll
            for (int q = 0; q < 4; q++) acc[j][q] = 0.0f;

        for (int c = 0; c < 16; c++) {
            if (c == 15) CPA_WAIT0(); else CPA_WAIT1();
            __syncthreads();
            if (c + 2 < 16) { STAGE_A(c + 2, (c + 2) % 3); CPA_COMMIT(); }
            uint32_t abb = sb + SM_A + (uint32_t)((c % 3) * 16384) + a_boff;
            uint32_t bbb = sb + SM_B + ((uint32_t)c << 13);
            #pragma unroll
            for (int kk = 0; kk < 4; kk++) {
                uint32_t kofs = (uint32_t)(kk * 32);
                uint32_t Ah[4];
                ldsm4(Ah, abb + ((a_kx + kofs) ^ a_xm));
                #pragma unroll
                for (int p = 0; p < 4; p++) {
                    uint32_t Bh[4];
                    ldsm4(Bh, bbb + (uint32_t)((p * 16 + brow) * 128)
                                  + ((b_kx + kofs) ^ b_xm));
                    mma16816(acc[2*p],     Ah, Bh[0], Bh[1]);
                    mma16816(acc[2*p + 1], Ah, Bh[2], Bh[3]);
                }
            }
        }
        __syncthreads();

        // D scratch overlays A buffers (all cp.async drained)
        float* D = (float*)(smb + SM_A);
        int r0 = w * 16 + (lane >> 2);
        int c0b = (lane & 3) * 2;
        #pragma unroll
        for (int j = 0; j < 8; j++) {
            int c0 = j * 8 + c0b;
            *(float2*)&D[r0 * DSTRIDE + c0]       = make_float2(acc[j][0], acc[j][1]);
            *(float2*)&D[(r0 + 8) * DSTRIDE + c0] = make_float2(acc[j][2], acc[j][3]);
        }
        // x-ready: alpha of step t-1 must be complete before reading g_x
        if (tid == 0) {
            unsigned lim = 128u * (unsigned)t;
            while (atomicAdd(&g_xdone, 0u) < lim) __nanosleep(32);
            __threadfence();
        }
        __syncthreads();

        // ---- fused LSTM pointwise epilogue ----
        {
            int row = tid >> 1;
            int ub  = (tid & 1) * 8;
            int b   = m0 + row;
            float xp0 = g_x[b * 2], xp1 = g_x[b * 2 + 1];
            const float* ibp = rnn_input + (size_t)b * Tt * 2 + (size_t)t * 2;
            float in0 = ibp[0], in1 = ibp[1];

            float* cptr = g_c + (size_t)b * Hh + nb * 16 + ub;
            float* hp   = hout + (size_t)b * Hh + nb * 16 + ub;
            float* op   = out + (size_t)b * Tt * Zz + (size_t)t * Zz + 2 + nb * 16 + ub;

            float cc[8], hnv[8];
            #pragma unroll
            for (int q = 0; q < 2; q++) {
                float4 v = *(float4*)(cptr + q * 4);
                cc[4*q] = v.x; cc[4*q+1] = v.y; cc[4*q+2] = v.z; cc[4*q+3] = v.w;
            }
            #pragma unroll
            for (int q = 0; q < 8; q++) {
                int ul = ub + q;
                int rg = nb * 64 + ul * 4;
                float4 bias = *(const float4*)(g_bias + rg);
                float bv[4] = {bias.x, bias.y, bias.z, bias.w};
                float gv[4];
                #pragma unroll
                for (int g2 = 0; g2 < 4; g2++) {
                    float4 wf = *(const float4*)(g_wfront + (size_t)(rg + g2) * 4);
                    gv[g2] = D[row * DSTRIDE + ul * 4 + g2] + bv[g2]
                           + xp0 * wf.x + xp1 * wf.y + in0 * wf.z + in1 * wf.w;
                }
                float ig = sigm(gv[0]), fg = sigm(gv[1]);
                float gg = tanhf(gv[2]), og = sigm(gv[3]);
                float cn = fg * cc[q] + ig * gg;
                cc[q] = cn;
                hnv[q] = og * tanhf(cn);
            }
            #pragma unroll
            for (int q = 0; q < 2; q++) {
                *(float4*)(cptr + q * 4) = make_float4(cc[4*q], cc[4*q+1], cc[4*q+2], cc[4*q+3]);
                *(float4*)(hp + q * 4)   = make_float4(hnv[4*q], hnv[4*q+1], hnv[4*q+2], hnv[4*q+3]);
            }
            #pragma unroll
            for (int q = 0; q < 4; q++)   // out row only 8B-aligned
                *(float2*)(op + q * 2) = make_float2(hnv[2*q], hnv[2*q+1]);

            // next-step A image (fp16, pre-swizzled)
            int mt = b >> 6, row64 = b & 63;
            int ch = nb >> 2;
            int kc = (nb & 3) * 16 + ub;
            uint32_t rel = (uint32_t)(row64 * 128)
                         + (((uint32_t)(kc * 2)) ^ ((row64 & 7) << 4));
            __half2 hx[4];
            #pragma unroll
            for (int j = 0; j < 4; j++)
                hx[j] = __floats2half2_rn(hnv[2*j], hnv[2*j+1]);
            char* idst = (char*)g_Aimg
                       + ((size_t)(((par ^ 1) * 4 + mt) * 16 + ch) << 13) + rel;
            *(uint4*)idst = *(uint4*)hx;
        }

        // ---- grid barrier (epoch target t+1) ----
        __syncthreads();
        if (tid == 0) {
            __threadfence();
            unsigned old = atomicAdd(&g_bar_arrive, 1u);
            if (old == 127u) {
                atomicExch(&g_bar_arrive, 0u);
                __threadfence();
                atomicAdd(&g_bar_epoch, 1u);
            } else {
                unsigned tgt = (unsigned)(t + 1);
                while (atomicAdd(&g_bar_epoch, 0u) < tgt) __nanosleep(64);
            }
            __threadfence();
        }
        __syncthreads();

        // ---- fused alpha/x section: 2 batch rows per CTA ----
        {
            int grp = tid >> 7, gt = tid & 127;
            int b = cta * 2 + grp;
            const float* hr = g_h[par ^ 1] + (size_t)b * Hh;
            const float* AW = (const float*)(smb + SM_AW);
            float s0 = 0.f, s1 = 0.f, s2 = 0.f, s3 = 0.f;
            #pragma unroll
            for (int k = gt; k < Hh; k += 128) {
                float hv = hr[k];
                s0 = fmaf(hv, AW[k],        s0);
                s1 = fmaf(hv, AW[1024 + k], s1);
                s2 = fmaf(hv, AW[2048 + k], s2);
                s3 = fmaf(hv, AW[3072 + k], s3);
            }
            #pragma unroll
            for (int off = 16; off > 0; off >>= 1) {
                s0 += __shfl_down_sync(0xffffffffu, s0, off);
                s1 += __shfl_down_sync(0xffffffffu, s1, off);
                s2 += __shfl_down_sync(0xffffffffu, s2, off);
                s3 += __shfl_down_sync(0xffffffffu, s3, off);
            }
            if (lane == 0) {
                red[w][0] = s0; red[w][1] = s1; red[w][2] = s2; red[w][3] = s3;
            }
            __syncthreads();
            if (gt == 0) {
                int wb = grp * 4;
                s0 = red[wb][0] + red[wb+1][0] + red[wb+2][0] + red[wb+3][0];
                s1 = red[wb][1] + red[wb+1][1] + red[wb+2][1] + red[wb+3][1];
                s2 = red[wb][2] + red[wb+1][2] + red[wb+2][2] + red[wb+3][2];
                s3 = red[wb][3] + red[wb+1][3] + red[wb+2][3] + red[wb+3][3];

                float x1 = g_x[b * 2 + 0], x2 = g_x[b * 2 + 1];
                float u  = rnn_input[(size_t)b * Tt * 2 + (size_t)t * 2];
                float ta = tau[(size_t)b * Tt + t];
                float a10 = -1.0f - 2.0f * x1 * x2;
                float a11 = 1.0f - x1 * x1;
                float xm0 = x1 + ta * x2;
                float xm1 = x2 + ta * (a10 * x1 + a11 * x2 + u);
                float al0 = sigm(s0 + ab0);
                float al1 = sigm(s1 + ab1);
                float xn0 = (1.0f - al0) * xm0 + al0 * (s2 + wb0);
                float xn1 = (1.0f - al1) * xm1 + al1 * (s3 + wb1);
                g_x[b * 2 + 0] = xn0;
                g_x[b * 2 + 1] = xn1;

                size_t ob = (size_t)b * Tt * Zz + (size_t)t * Zz;
                out[ob + 0] = xn0;
                out[ob + 1] = xn1;
                size_t cb = COEF_OFF + (size_t)b * Tt * 2 + (size_t)t * 2;
                out[cb + 0] = al0;
                out[cb + 1] = al1;
                if (b == 0) {
                    size_t mo = MATS_OFF + (size_t)t * 4;
                    out[mo + 0] = 0.0f;
                    out[mo + 1] = 1.0f;
                    out[mo + 2] = a10;
                    out[mo + 3] = a11;
                }
                __threadfence();
            }
            __syncthreads();
            if (tid == 0) atomicAdd(&g_xdone, 1u);
        }
        #undef STAGE_A
    }
}

// ---------------------------------------------------------------------------
__global__ void finalize(const float* __restrict__ c_z0,
                         float* __restrict__ out) {
    int i = blockIdx.x * blockDim.x + threadIdx.x;
    if (i >= Bb * Zz) return;
    int b = i / Zz, z = i - b * Zz;
    float zv, cv;
    if (z < 2) {
        zv = g_x[b * 2 + z];
        cv = c_z0[(size_t)b * Zz + z];
    } else {
        zv = g_h[0][(size_t)b * Hh + z - 2];   // t=255 writes g_h[0]
        cv = g_c[(size_t)b * Hh + z - 2];
    }
    out[ZF_OFF  + i] = zv;
    out[CZF_OFF + i] = cv;
}

// ---------------------------------------------------------------------------
extern "C" void kernel_launch(void* const* d_in, const int* in_sizes, int n_in,
                              void* d_out, int out_size) {
    const float* rnn_input = (const float*)d_in[0];
    const float* tau       = (const float*)d_in[1];
    const float* z0        = (const float*)d_in[2];
    const float* c_z0      = (const float*)d_in[3];
    const float* WU_w      = (const float*)d_in[4];
    const float* WU_b      = (const float*)d_in[5];
    const float* alpha_w   = (const float*)d_in[6];
    const float* alpha_b   = (const float*)d_in[7];
    const float* Wx_w      = (const float*)d_in[8];
    const float* Wx_b      = (const float*)d_in[9];
    float* out = (float*)d_out;

    const int smem_bytes = SM_TOT + 1024 + 128;   // 197760
    cudaFuncSetAttribute(lstm_persist,
                         cudaFuncAttributeMaxDynamicSharedMemorySize, smem_bytes);

    repack<<<dim3(64, 16), 256>>>(WU_w);
    prep_misc<<<16, 256>>>(WU_w, WU_b);
    init_state<<<(Bb * Hh + 255) / 256, 256>>>(z0, c_z0);

    lstm_persist<<<128, 256, smem_bytes>>>(rnn_input, tau, alpha_w, alpha_b,
                                           Wx_w, Wx_b, out);

    finalize<<<(Bb * Zz + 127) / 128, 128>>>(c_z0, out);
}

// round 10
// speedup vs baseline: 6.2219x; 1.0839x over previous
#include <cuda_runtime.h>
#include <cuda_fp16.h>
#include <math.h>
#include <stdint.h>

#define Bb   256
#define Tt   256
#define Hh   1024
#define Zz   1026
#define KW   1028

#define ZF_OFF   ((long long)Bb * Tt * Zz)
#define CZF_OFF  (ZF_OFF + (long long)Bb * Zz)
#define COEF_OFF (CZF_OFF + (long long)Bb * Zz)
#define MATS_OFF (COEF_OFF + (long long)Bb * Tt * 2)

// Persistent device state
__device__ float g_h[2][Bb * Hh];     // final h only (finalize)
__device__ float g_c[Bb * Hh];
__device__ float g_x[Bb * 2];
__device__ float g_salpha[Bb * 4];    // alpha/Wx partial sums
// fp16 pre-swizzled images (8KB blocks: 64 rows x 64 k, 128B rows, SW128):
__device__ __align__(128) __half g_Wimg[64 * 16 * 4096];       // [nb][ch]
__device__ __align__(128) __half g_Aimg[2 * 4 * 16 * 4096];    // [par][mt][ch]
__device__ float g_bias[4096];
__device__ float g_wfront[4096 * 4];
// persistent-kernel sync state
__device__ unsigned g_bar_arrive;
__device__ unsigned g_bar_epoch;
__device__ unsigned g_xdone;

__device__ __forceinline__ float sigm(float x) { return 1.0f / (1.0f + expf(-x)); }

__device__ __forceinline__ uint32_t smem_u32(const void* p) {
    uint32_t a;
    asm("{ .reg .u64 t; cvta.to.shared.u64 t, %1; cvt.u32.u64 %0, t; }" : "=r"(a) : "l"(p));
    return a;
}

__device__ __forceinline__ void ldsm4(uint32_t* r, uint32_t addr) {
    asm volatile("ldmatrix.sync.aligned.m8n8.x4.shared.b16 {%0,%1,%2,%3}, [%4];"
                 : "=r"(r[0]), "=r"(r[1]), "=r"(r[2]), "=r"(r[3]) : "r"(addr));
}

__device__ __forceinline__ void mma16816(float (&d)[4], const uint32_t* a,
                                         uint32_t b0, uint32_t b1) {
    asm volatile(
        "mma.sync.aligned.m16n8k16.row.col.f32.f16.f16.f32 "
        "{%0,%1,%2,%3}, {%4,%5,%6,%7}, {%8,%9}, {%0,%1,%2,%3};"
        : "+f"(d[0]), "+f"(d[1]), "+f"(d[2]), "+f"(d[3])
        : "r"(a[0]), "r"(a[1]), "r"(a[2]), "r"(a[3]), "r"(b0), "r"(b1));
}

#define CPA(dst, src) \
    asm volatile("cp.async.cg.shared.global [%0], [%1], 16;" \
                 :: "r"(dst), "l"(src) : "memory")
#define CPA_COMMIT() asm volatile("cp.async.commit_group;" ::: "memory")
#define CPA_WAIT0()  asm volatile("cp.async.wait_group 0;" ::: "memory")
#define CPA_WAIT3()  asm volatile("cp.async.wait_group 3;" ::: "memory")

// SMEM layout (relative to 1024-aligned base)
#define SM_B    0        // 131072: resident B (16 blocks x 8KB)
#define SM_A    131072   // 65536: per-warp A rings (8 warps x 4 stages x 2KB)
#define SM_C    196608   // 10240: c state, 128 rows x stride 20 floats
#define SM_MISC 206848   // 2048: bias(64f) | wfront(256f) | aw(64f)
#define SM_TOT  208896
#define CSTRIDE 20
#define DSTRIDE 66

// ---------------------------------------------------------------------------
__global__ void repack(const float* __restrict__ WU_w) {
    int nb = blockIdx.x, ch = blockIdx.y;
    char* base = (char*)g_Wimg + ((size_t)(nb * 16 + ch) << 13);
    for (int e = threadIdx.x; e < 4096; e += 256) {
        int r = e >> 6, c = e & 63;
        int rg = nb * 64 + r;
        int u = rg >> 2, g = rg & 3;
        float w = WU_w[(size_t)(g * Hh + u) * KW + 4 + ch * 64 + c];
        uint32_t off = (uint32_t)(r * 128 + c * 2);
        off ^= (off >> 3) & 0x70;
        *(__half*)(base + off) = __float2half_rn(w);
    }
}

__global__ void prep_misc(const float* __restrict__ WU_w,
                          const float* __restrict__ WU_b) {
    int r = blockIdx.x * 256 + threadIdx.x;
    if (r >= 4096) return;
    int u = r >> 2, g = r & 3;
    g_bias[r] = WU_b[g * Hh + u];
    const float* src = WU_w + (size_t)(g * Hh + u) * KW;
    #pragma unroll
    for (int j = 0; j < 4; j++) g_wfront[r * 4 + j] = src[j];
}

__global__ void init_state(const float* __restrict__ z0,
                           const float* __restrict__ c_z0) {
    int i = blockIdx.x * blockDim.x + threadIdx.x;
    if (i == 0) { g_bar_arrive = 0u; g_bar_epoch = 0u; g_xdone = 0u; }
    if (i < Bb * 4) g_salpha[i] = 0.0f;
    if (i < Bb * Hh) {
        int b = i / Hh, j = i - b * Hh;
        float hv = z0[(size_t)b * Zz + 2 + j];
        g_c[i] = c_z0[(size_t)b * Zz + 2 + j];
        int mt = b >> 6, row = b & 63, ch = j >> 6, kc = j & 63;
        uint32_t rel = (uint32_t)(row * 128 + kc * 2);
        rel ^= (rel >> 3) & 0x70;
        *(__half*)((char*)g_Aimg + ((size_t)(mt * 16 + ch) << 13) + rel)
            = __float2half_rn(hv);
    }
    if (i < Bb * 2) {
        int b = i >> 1, s = i & 1;
        g_x[i] = z0[(size_t)b * Zz + s];
    }
}

// ---------------------------------------------------------------------------
// Persistent kernel: grid 128 (mb = cta&1, nb = cta>>1), block 256, 1 CTA/SM
// ---------------------------------------------------------------------------
__global__ __launch_bounds__(256) void lstm_persist(
    const float* __restrict__ rnn_input, const float* __restrict__ tau,
    const float* __restrict__ alpha_w,   const float* __restrict__ alpha_b,
    const float* __restrict__ Wx_w,      const float* __restrict__ Wx_b,
    float* __restrict__ out)
{
    extern __shared__ char smraw[];
    uint32_t sb0 = smem_u32(smraw);
    uint32_t pad = (1024u - (sb0 & 1023u)) & 1023u;
    char* smb = smraw + pad;
    uint32_t sb = sb0 + pad;

    int tid = threadIdx.x;
    int cta = blockIdx.x;
    int mb = cta & 1, nb = cta >> 1;
    int m0 = mb * 128;

    int w = tid >> 5, lane = tid & 31;
    uint32_t wring = sb + SM_A + ((uint32_t)w << 13);   // 8KB ring per warp
    uint32_t a_kx = (uint32_t)((lane >> 4) * 16);
    uint32_t a_xm = (uint32_t)(((lane & 15) & 7) << 4);
    uint32_t a_ro = (uint32_t)((lane & 15) * 128);
    int brow = (lane & 7) + ((lane >> 4) & 1) * 8;
    uint32_t b_kx = (uint32_t)(((lane >> 3) & 1) * 16);
    uint32_t b_xm = (uint32_t)((lane & 7) << 4);

    float* sc    = (float*)(smb + SM_C);
    float* sbias = (float*)(smb + SM_MISC);
    float* swf   = sbias + 64;
    float* saw   = swf + 256;

    // ---- prologue: resident B (128KB) + misc + c state ----
    {
        const char* bsrc = (const char*)g_Wimg + ((size_t)(nb * 16) << 13);
        #pragma unroll
        for (int it = 0; it < 32; it++) {
            uint32_t f = (uint32_t)((it * 256 + tid) * 16);
            CPA(sb + SM_B + f, bsrc + f);
        }
        CPA_COMMIT();
        if (tid < 64)  sbias[tid] = g_bias[nb * 64 + tid];
        swf[tid] = g_wfront[nb * 256 + tid];
        if (tid < 16) {
            saw[tid]      = alpha_w[nb * 16 + tid];
            saw[16 + tid] = alpha_w[1024 + nb * 16 + tid];
            saw[32 + tid] = Wx_w[nb * 16 + tid];
            saw[48 + tid] = Wx_w[1024 + nb * 16 + tid];
        }
        {
            int row = tid >> 1, ub = (tid & 1) * 8;
            const float* csrc = g_c + (size_t)(m0 + row) * Hh + nb * 16 + ub;
            float4 v0 = *(const float4*)csrc;
            float4 v1 = *(const float4*)(csrc + 4);
            *(float4*)(sc + row * CSTRIDE + ub)     = v0;
            *(float4*)(sc + row * CSTRIDE + ub + 4) = v1;
        }
        CPA_WAIT0();
        __syncthreads();
    }
    float ab0 = alpha_b[0], ab1 = alpha_b[1];
    float wb0 = Wx_b[0],    wb1 = Wx_b[1];

    for (int t = 0; t < Tt; t++) {
        int par = t & 1;
        const char* awsrc = (const char*)g_Aimg
            + ((size_t)((par * 4 + mb * 2 + (w >> 2)) * 16) << 13)
            + (uint32_t)((w & 3) * 2048);

        #define STAGE_W(ch_, s_) do {                                   \
            const char* src_ = awsrc + ((size_t)(ch_) << 13);           \
            uint32_t d_ = wring + (uint32_t)((s_) * 2048);              \
            _Pragma("unroll")                                           \
            for (int i_ = 0; i_ < 4; i_++) {                            \
                uint32_t f_ = (uint32_t)((i_ * 32 + lane) * 16);        \
                CPA(d_ + f_, src_ + f_);                                \
            }                                                           \
        } while (0)

        STAGE_W(0, 0); CPA_COMMIT();
        STAGE_W(1, 1); CPA_COMMIT();
        STAGE_W(2, 2); CPA_COMMIT();

        float acc[8][4];
        #pragma unroll
        for (int j = 0; j < 8; j++)
            #pragma unroll
            for (int q = 0; q < 4; q++) acc[j][q] = 0.0f;

        for (int c = 0; c < 16; c++) {
            if (c + 3 < 16) STAGE_W(c + 3, (c + 3) & 3);
            CPA_COMMIT();                       // empty group at tail: keeps count
            CPA_WAIT3();
            __syncwarp();
            uint32_t abb = wring + (uint32_t)((c & 3) * 2048) + a_ro;
            uint32_t bbb = sb + SM_B + ((uint32_t)c << 13);
            #pragma unroll
            for (int kk = 0; kk < 4; kk++) {
                uint32_t kofs = (uint32_t)(kk * 32);
                uint32_t Ah[4];
                ldsm4(Ah, abb + ((a_kx + kofs) ^ a_xm));
                #pragma unroll
                for (int p = 0; p < 4; p++) {
                    uint32_t Bh[4];
                    ldsm4(Bh, bbb + (uint32_t)((p * 16 + brow) * 128)
                                  + ((b_kx + kofs) ^ b_xm));
                    mma16816(acc[2*p],     Ah, Bh[0], Bh[1]);
                    mma16816(acc[2*p + 1], Ah, Bh[2], Bh[3]);
                }
            }
        }
        CPA_WAIT0();
        #undef STAGE_W

        // wait x of step t-1 final, and sync all warps before D overlays rings
        if (tid == 0) {
            unsigned lim = 128u * (unsigned)t;
            while (atomicAdd(&g_xdone, 0u) < lim) __nanosleep(32);
            __threadfence();
        }
        __syncthreads();

        float* D = (float*)(smb + SM_A);
        {
            int r0 = w * 16 + (lane >> 2);
            int c0b = (lane & 3) * 2;
            #pragma unroll
            for (int j = 0; j < 8; j++) {
                int c0 = j * 8 + c0b;
                *(float2*)&D[r0 * DSTRIDE + c0]       = make_float2(acc[j][0], acc[j][1]);
                *(float2*)&D[(r0 + 8) * DSTRIDE + c0] = make_float2(acc[j][2], acc[j][3]);
            }
        }
        __syncthreads();

        // ---- fused LSTM pointwise epilogue + alpha partials ----
        {
            int row = tid >> 1;
            int ub  = (tid & 1) * 8;
            int b   = m0 + row;
            float xp0 = g_x[b * 2], xp1 = g_x[b * 2 + 1];
            const float* ibp = rnn_input + (size_t)b * Tt * 2 + (size_t)t * 2;
            float in0 = ibp[0], in1 = ibp[1];

            float* cp = sc + row * CSTRIDE + ub;
            float* op = out + (size_t)b * Tt * Zz + (size_t)t * Zz + 2 + nb * 16 + ub;

            float cc[8], hnv[8];
            #pragma unroll
            for (int q = 0; q < 2; q++) {
                float4 v = *(float4*)(cp + q * 4);
                cc[4*q] = v.x; cc[4*q+1] = v.y; cc[4*q+2] = v.z; cc[4*q+3] = v.w;
            }
            float s0 = 0.f, s1 = 0.f, s2 = 0.f, s3 = 0.f;
            #pragma unroll
            for (int q = 0; q < 8; q++) {
                int ul = ub + q;
                float4 bias4 = *(float4*)(sbias + ul * 4);
                float bv[4] = {bias4.x, bias4.y, bias4.z, bias4.w};
                float gv[4];
                #pragma unroll
                for (int g2 = 0; g2 < 4; g2++) {
                    float4 wf = *(float4*)(swf + (ul * 4 + g2) * 4);
                    gv[g2] = D[row * DSTRIDE + ul * 4 + g2] + bv[g2]
                           + xp0 * wf.x + xp1 * wf.y + in0 * wf.z + in1 * wf.w;
                }
                float ig = sigm(gv[0]), fg = sigm(gv[1]);
                float gg = tanhf(gv[2]), og = sigm(gv[3]);
                float cn = fg * cc[q] + ig * gg;
                cc[q] = cn;
                float hn = og * tanhf(cn);
                hnv[q] = hn;
                s0 = fmaf(hn, saw[ul],      s0);
                s1 = fmaf(hn, saw[16 + ul], s1);
                s2 = fmaf(hn, saw[32 + ul], s2);
                s3 = fmaf(hn, saw[48 + ul], s3);
            }
            #pragma unroll
            for (int q = 0; q < 2; q++)
                *(float4*)(cp + q * 4) = make_float4(cc[4*q], cc[4*q+1], cc[4*q+2], cc[4*q+3]);
            #pragma unroll
            for (int q = 0; q < 4; q++)   // out row only 8B-aligned
                *(float2*)(op + q * 2) = make_float2(hnv[2*q], hnv[2*q+1]);

            // alpha partials: combine (tid, tid^1) then atomicAdd
            s0 += __shfl_xor_sync(0xffffffffu, s0, 1);
            s1 += __shfl_xor_sync(0xffffffffu, s1, 1);
            s2 += __shfl_xor_sync(0xffffffffu, s2, 1);
            s3 += __shfl_xor_sync(0xffffffffu, s3, 1);
            if ((tid & 1) == 0) {
                atomicAdd(&g_salpha[b * 4 + 0], s0);
                atomicAdd(&g_salpha[b * 4 + 1], s1);
                atomicAdd(&g_salpha[b * 4 + 2], s2);
                atomicAdd(&g_salpha[b * 4 + 3], s3);
            }

            // next-step A image (fp16, pre-swizzled)
            int mt = b >> 6, row64 = b & 63;
            int ch = nb >> 2;
            int kc = (nb & 3) * 16 + ub;
            uint32_t rel = (uint32_t)(row64 * 128)
                         + (((uint32_t)(kc * 2)) ^ ((row64 & 7) << 4));
            __half2 hx[4];
            #pragma unroll
            for (int j = 0; j < 4; j++)
                hx[j] = __floats2half2_rn(hnv[2*j], hnv[2*j+1]);
            char* idst = (char*)g_Aimg
                       + ((size_t)(((par ^ 1) * 4 + mt) * 16 + ch) << 13) + rel;
            *(uint4*)idst = *(uint4*)hx;

            if (t == Tt - 1) {   // final h/c to global for finalize
                float* hp = g_h[0] + (size_t)b * Hh + nb * 16 + ub;
                float* cg = g_c + (size_t)b * Hh + nb * 16 + ub;
                #pragma unroll
                for (int q = 0; q < 2; q++) {
                    *(float4*)(hp + q * 4) = make_float4(hnv[4*q], hnv[4*q+1], hnv[4*q+2], hnv[4*q+3]);
                    *(float4*)(cg + q * 4) = make_float4(cc[4*q], cc[4*q+1], cc[4*q+2], cc[4*q+3]);
                }
            }
        }

        // ---- grid barrier (epoch target t+1) ----
        __syncthreads();
        if (tid == 0) {
            __threadfence();
            unsigned old = atomicAdd(&g_bar_arrive, 1u);
            if (old == 127u) {
                atomicExch(&g_bar_arrive, 0u);
                __threadfence();
                atomicAdd(&g_bar_epoch, 1u);
            } else {
                unsigned tgt = (unsigned)(t + 1);
                while (atomicAdd(&g_bar_epoch, 0u) < tgt) __nanosleep(64);
            }
            __threadfence();
        }
        __syncthreads();

        // ---- x update: CTA handles b = cta*2, cta*2+1 (tid 0 only) ----
        if (tid == 0) {
            #pragma unroll
            for (int bi = 0; bi < 2; bi++) {
                int b = cta * 2 + bi;
                float s0 = g_salpha[b * 4 + 0];
                float s1 = g_salpha[b * 4 + 1];
                float s2 = g_salpha[b * 4 + 2];
                float s3 = g_salpha[b * 4 + 3];
                g_salpha[b * 4 + 0] = 0.f; g_salpha[b * 4 + 1] = 0.f;
                g_salpha[b * 4 + 2] = 0.f; g_salpha[b * 4 + 3] = 0.f;

                float x1 = g_x[b * 2 + 0], x2 = g_x[b * 2 + 1];
                float u  = rnn_input[(size_t)b * Tt * 2 + (size_t)t * 2];
                float ta = tau[(size_t)b * Tt + t];
                float a10 = -1.0f - 2.0f * x1 * x2;
                float a11 = 1.0f - x1 * x1;
                float xm0 = x1 + ta * x2;
                float xm1 = x2 + ta * (a10 * x1 + a11 * x2 + u);
                float al0 = sigm(s0 + ab0);
                float al1 = sigm(s1 + ab1);
                float xn0 = (1.0f - al0) * xm0 + al0 * (s2 + wb0);
                float xn1 = (1.0f - al1) * xm1 + al1 * (s3 + wb1);
                g_x[b * 2 + 0] = xn0;
                g_x[b * 2 + 1] = xn1;

                size_t ob = (size_t)b * Tt * Zz + (size_t)t * Zz;
                out[ob + 0] = xn0;
                out[ob + 1] = xn1;
                size_t cb = COEF_OFF + (size_t)b * Tt * 2 + (size_t)t * 2;
                out[cb + 0] = al0;
                out[cb + 1] = al1;
                if (b == 0) {
                    size_t mo = MATS_OFF + (size_t)t * 4;
                    out[mo + 0] = 0.0f;
                    out[mo + 1] = 1.0f;
                    out[mo + 2] = a10;
                    out[mo + 3] = a11;
                }
            }
            __threadfence();
            atomicAdd(&g_xdone, 1u);
        }
    }
}

// ---------------------------------------------------------------------------
__global__ void finalize(const float* __restrict__ c_z0,
                         float* __restrict__ out) {
    int i = blockIdx.x * blockDim.x + threadIdx.x;
    if (i >= Bb * Zz) return;
    int b = i / Zz, z = i - b * Zz;
    float zv, cv;
    if (z < 2) {
        zv = g_x[b * 2 + z];
        cv = c_z0[(size_t)b * Zz + z];
    } else {
        zv = g_h[0][(size_t)b * Hh + z - 2];
        cv = g_c[(size_t)b * Hh + z - 2];
    }
    out[ZF_OFF  + i] = zv;
    out[CZF_OFF + i] = cv;
}

// ---------------------------------------------------------------------------
extern "C" void kernel_launch(void* const* d_in, const int* in_sizes, int n_in,
                              void* d_out, int out_size) {
    const float* rnn_input = (const float*)d_in[0];
    const float* tau       = (const float*)d_in[1];
    const float* z0        = (const float*)d_in[2];
    const float* c_z0      = (const float*)d_in[3];
    const float* WU_w      = (const float*)d_in[4];
    const float* WU_b      = (const float*)d_in[5];
    const float* alpha_w   = (const float*)d_in[6];
    const float* alpha_b   = (const float*)d_in[7];
    const float* Wx_w      = (const float*)d_in[8];
    const float* Wx_b      = (const float*)d_in[9];
    float* out = (float*)d_out;

    const int smem_bytes = SM_TOT + 1024 + 128;   // 210048
    cudaFuncSetAttribute(lstm_persist,
                         cudaFuncAttributeMaxDynamicSharedMemorySize, smem_bytes);

    repack<<<dim3(64, 16), 256>>>(WU_w);
    prep_misc<<<16, 256>>>(WU_w, WU_b);
    init_state<<<(Bb * Hh + 255) / 256, 256>>>(z0, c_z0);

    lstm_persist<<<128, 256, smem_bytes>>>(rnn_input, tau, alpha_w, alpha_b,
                                           Wx_w, Wx_b, out);

    finalize<<<(Bb * Zz + 127) / 128, 128>>>(c_z0, out);
}

// round 11
// speedup vs baseline: 7.3221x; 1.1768x over previous
#include <cuda_runtime.h>
#include <cuda_fp16.h>
#include <math.h>
#include <stdint.h>

#define Bb   256
#define Tt   256
#define Hh   1024
#define Zz   1026
#define KW   1028

#define ZF_OFF   ((long long)Bb * Tt * Zz)
#define CZF_OFF  (ZF_OFF + (long long)Bb * Zz)
#define COEF_OFF (CZF_OFF + (long long)Bb * Zz)
#define MATS_OFF (COEF_OFF + (long long)Bb * Tt * 2)

// Persistent device state
__device__ float g_h[Bb * Hh];                    // final h (finalize only)
__device__ float g_c[Bb * Hh];                    // init + final c
__device__ float g_x[Bb * 2];                     // init + final x
__device__ __align__(16) float g_salpha[Bb * 4];  // CUMULATIVE alpha/Wx sums
// fp16 pre-swizzled images (8KB blocks: 64 rows x 64 k, 128B rows, SW128):
__device__ __align__(128) __half g_Wimg[64 * 16 * 4096];       // [nb][ch]
__device__ __align__(128) __half g_Aimg[2 * 4 * 16 * 4096];    // [par][mt][ch]
__device__ float g_bias[4096];
__device__ float g_wfront[4096 * 4];
// grid barrier (cumulative counters, never reset)
__device__ unsigned g_bar_arrive;
__device__ unsigned g_bar_epoch;

// fast sigmoid/tanh via EX2+RCP (err ~1e-7, MUFU only)
__device__ __forceinline__ float fsigm(float x) {
    float e, r;
    asm("ex2.approx.f32 %0, %1;" : "=f"(e) : "f"(x * -1.442695041f));
    asm("rcp.approx.f32 %0, %1;" : "=f"(r) : "f"(1.0f + e));
    return r;
}
__device__ __forceinline__ float ftanh(float x) {
    return fmaf(2.0f, fsigm(2.0f * x), -1.0f);
}

__device__ __forceinline__ uint32_t smem_u32(const void* p) {
    uint32_t a;
    asm("{ .reg .u64 t; cvta.to.shared.u64 t, %1; cvt.u32.u64 %0, t; }" : "=r"(a) : "l"(p));
    return a;
}

__device__ __forceinline__ void ldsm4(uint32_t* r, uint32_t addr) {
    asm volatile("ldmatrix.sync.aligned.m8n8.x4.shared.b16 {%0,%1,%2,%3}, [%4];"
                 : "=r"(r[0]), "=r"(r[1]), "=r"(r[2]), "=r"(r[3]) : "r"(addr));
}

__device__ __forceinline__ void mma16816(float (&d)[4], const uint32_t* a,
                                         uint32_t b0, uint32_t b1) {
    asm volatile(
        "mma.sync.aligned.m16n8k16.row.col.f32.f16.f16.f32 "
        "{%0,%1,%2,%3}, {%4,%5,%6,%7}, {%8,%9}, {%0,%1,%2,%3};"
        : "+f"(d[0]), "+f"(d[1]), "+f"(d[2]), "+f"(d[3])
        : "r"(a[0]), "r"(a[1]), "r"(a[2]), "r"(a[3]), "r"(b0), "r"(b1));
}

#define CPA(dst, src) \
    asm volatile("cp.async.cg.shared.global [%0], [%1], 16;" \
                 :: "r"(dst), "l"(src) : "memory")
#define CPA_COMMIT() asm volatile("cp.async.commit_group;" ::: "memory")
#define CPA_WAIT0()  asm volatile("cp.async.wait_group 0;" ::: "memory")
#define CPA_WAIT3()  asm volatile("cp.async.wait_group 3;" ::: "memory")

// SMEM layout (relative to 1024-aligned base)
#define SM_B    0        // 131072: resident B (16 x 8KB)
#define SM_A    131072   // 65536: per-warp A rings (8 warps x 4 x 2KB)
#define SM_C    196608   // 10240: c state (128 rows x stride 20)
#define SM_MISC 206848   // 1536: bias(64f) | wfront(256f) | aw(64f)
#define SM_SX   208384   // 1024: x state (128 rows x 2)
#define SM_PREV 209408   // 2048: prev cumulative salpha (128 x 4)
#define SM_TOT  211456
#define CSTRIDE 20
#define DSTRIDE 66

// ---------------------------------------------------------------------------
__global__ void repack(const float* __restrict__ WU_w) {
    int nb = blockIdx.x, ch = blockIdx.y;
    char* base = (char*)g_Wimg + ((size_t)(nb * 16 + ch) << 13);
    for (int e = threadIdx.x; e < 4096; e += 256) {
        int r = e >> 6, c = e & 63;
        int rg = nb * 64 + r;
        int u = rg >> 2, g = rg & 3;
        float w = WU_w[(size_t)(g * Hh + u) * KW + 4 + ch * 64 + c];
        uint32_t off = (uint32_t)(r * 128 + c * 2);
        off ^= (off >> 3) & 0x70;
        *(__half*)(base + off) = __float2half_rn(w);
    }
}

__global__ void prep_misc(const float* __restrict__ WU_w,
                          const float* __restrict__ WU_b) {
    int r = blockIdx.x * 256 + threadIdx.x;
    if (r >= 4096) return;
    int u = r >> 2, g = r & 3;
    g_bias[r] = WU_b[g * Hh + u];
    const float* src = WU_w + (size_t)(g * Hh + u) * KW;
    #pragma unroll
    for (int j = 0; j < 4; j++) g_wfront[r * 4 + j] = src[j];
}

__global__ void init_state(const float* __restrict__ z0,
                           const float* __restrict__ c_z0) {
    int i = blockIdx.x * blockDim.x + threadIdx.x;
    if (i == 0) { g_bar_arrive = 0u; g_bar_epoch = 0u; }
    if (i < Bb * 4) g_salpha[i] = 0.0f;
    if (i < Bb * Hh) {
        int b = i / Hh, j = i - b * Hh;
        float hv = z0[(size_t)b * Zz + 2 + j];
        g_c[i] = c_z0[(size_t)b * Zz + 2 + j];
        int mt = b >> 6, row = b & 63, ch = j >> 6, kc = j & 63;
        uint32_t rel = (uint32_t)(row * 128 + kc * 2);
        rel ^= (rel >> 3) & 0x70;
        *(__half*)((char*)g_Aimg + ((size_t)(mt * 16 + ch) << 13) + rel)
            = __float2half_rn(hv);
    }
    if (i < Bb * 2) {
        int b = i >> 1, s = i & 1;
        g_x[i] = z0[(size_t)b * Zz + s];
    }
}

// ---------------------------------------------------------------------------
// Persistent kernel: grid 128 (mb = cta&1, nb = cta>>1), block 256, 1 CTA/SM
// ---------------------------------------------------------------------------
__global__ __launch_bounds__(256) void lstm_persist(
    const float* __restrict__ rnn_input, const float* __restrict__ tau,
    const float* __restrict__ alpha_w,   const float* __restrict__ alpha_b,
    const float* __restrict__ Wx_w,      const float* __restrict__ Wx_b,
    float* __restrict__ out)
{
    extern __shared__ char smraw[];
    uint32_t sb0 = smem_u32(smraw);
    uint32_t pad = (1024u - (sb0 & 1023u)) & 1023u;
    char* smb = smraw + pad;
    uint32_t sb = sb0 + pad;

    int tid = threadIdx.x;
    int cta = blockIdx.x;
    int mb = cta & 1, nb = cta >> 1;
    int m0 = mb * 128;

    int w = tid >> 5, lane = tid & 31;
    uint32_t wring = sb + SM_A + ((uint32_t)w << 13);
    uint32_t a_kx = (uint32_t)((lane >> 4) * 16);
    uint32_t a_xm = (uint32_t)(((lane & 15) & 7) << 4);
    uint32_t a_ro = (uint32_t)((lane & 15) * 128);
    int brow = (lane & 7) + ((lane >> 4) & 1) * 8;
    uint32_t b_kx = (uint32_t)(((lane >> 3) & 1) * 16);
    uint32_t b_xm = (uint32_t)((lane & 7) << 4);

    float* sc    = (float*)(smb + SM_C);
    float* sbias = (float*)(smb + SM_MISC);
    float* swf   = sbias + 64;
    float* saw   = swf + 256;
    float* sx    = (float*)(smb + SM_SX);
    float* sprev = (float*)(smb + SM_PREV);

    // ---- prologue ----
    {
        const char* bsrc = (const char*)g_Wimg + ((size_t)(nb * 16) << 13);
        #pragma unroll
        for (int it = 0; it < 32; it++) {
            uint32_t f = (uint32_t)((it * 256 + tid) * 16);
            CPA(sb + SM_B + f, bsrc + f);
        }
        CPA_COMMIT();
        if (tid < 64)  sbias[tid] = g_bias[nb * 64 + tid];
        swf[tid] = g_wfront[nb * 256 + tid];
        if (tid < 16) {
            saw[tid]      = alpha_w[nb * 16 + tid];
            saw[16 + tid] = alpha_w[1024 + nb * 16 + tid];
            saw[32 + tid] = Wx_w[nb * 16 + tid];
            saw[48 + tid] = Wx_w[1024 + nb * 16 + tid];
        }
        {
            int row = tid >> 1, ub = (tid & 1) * 8;
            const float* csrc = g_c + (size_t)(m0 + row) * Hh + nb * 16 + ub;
            float4 v0 = *(const float4*)csrc;
            float4 v1 = *(const float4*)(csrc + 4);
            *(float4*)(sc + row * CSTRIDE + ub)     = v0;
            *(float4*)(sc + row * CSTRIDE + ub + 4) = v1;
        }
        if (tid < 128) {
            sx[tid * 2]     = g_x[(m0 + tid) * 2];
            sx[tid * 2 + 1] = g_x[(m0 + tid) * 2 + 1];
            *(float4*)(sprev + tid * 4) = make_float4(0.f, 0.f, 0.f, 0.f);
        }
        CPA_WAIT0();
        __syncthreads();
    }
    float ab0 = alpha_b[0], ab1 = alpha_b[1];
    float wb0 = Wx_b[0],    wb1 = Wx_b[1];

    for (int t = 0; t < Tt; t++) {
        int par = t & 1;
        const char* awsrc = (const char*)g_Aimg
            + ((size_t)((par * 4 + mb * 2 + (w >> 2)) * 16) << 13)
            + (uint32_t)((w & 3) * 2048);

        #define STAGE_W(ch_, s_) do {                                   \
            const char* src_ = awsrc + ((size_t)(ch_) << 13);           \
            uint32_t d_ = wring + (uint32_t)((s_) * 2048);              \
            _Pragma("unroll")                                           \
            for (int i_ = 0; i_ < 4; i_++) {                            \
                uint32_t f_ = (uint32_t)((i_ * 32 + lane) * 16);        \
                CPA(d_ + f_, src_ + f_);                                \
            }                                                           \
        } while (0)

        STAGE_W(0, 0); CPA_COMMIT();
        STAGE_W(1, 1); CPA_COMMIT();
        STAGE_W(2, 2); CPA_COMMIT();

        float acc[8][4];
        #pragma unroll
        for (int j = 0; j < 8; j++)
            #pragma unroll
            for (int q = 0; q < 4; q++) acc[j][q] = 0.0f;

        for (int c = 0; c < 16; c++) {
            if (c + 3 < 16) STAGE_W(c + 3, (c + 3) & 3);
            CPA_COMMIT();
            CPA_WAIT3();
            __syncwarp();
            uint32_t abb = wring + (uint32_t)((c & 3) * 2048) + a_ro;
            uint32_t bbb = sb + SM_B + ((uint32_t)c << 13);
            #pragma unroll
            for (int kk = 0; kk < 4; kk++) {
                uint32_t kofs = (uint32_t)(kk * 32);
                uint32_t Ah[4];
                ldsm4(Ah, abb + ((a_kx + kofs) ^ a_xm));
                #pragma unroll
                for (int p = 0; p < 4; p++) {
                    uint32_t Bh[4];
                    ldsm4(Bh, bbb + (uint32_t)((p * 16 + brow) * 128)
                                  + ((b_kx + kofs) ^ b_xm));
                    mma16816(acc[2*p],     Ah, Bh[0], Bh[1]);
                    mma16816(acc[2*p + 1], Ah, Bh[2], Bh[3]);
                }
            }
        }
        CPA_WAIT0();
        #undef STAGE_W
        __syncthreads();   // all rings consumed; D may overlay

        float* D = (float*)(smb + SM_A);
        {
            int r0 = w * 16 + (lane >> 2);
            int c0b = (lane & 3) * 2;
            #pragma unroll
            for (int j = 0; j < 8; j++) {
                int c0 = j * 8 + c0b;
                *(float2*)&D[r0 * DSTRIDE + c0]       = make_float2(acc[j][0], acc[j][1]);
                *(float2*)&D[(r0 + 8) * DSTRIDE + c0] = make_float2(acc[j][2], acc[j][3]);
            }
        }
        __syncthreads();

        // ---- fused LSTM pointwise epilogue + alpha partial atomics ----
        {
            int row = tid >> 1;
            int ub  = (tid & 1) * 8;
            int b   = m0 + row;
            float xp0 = sx[row * 2], xp1 = sx[row * 2 + 1];
            const float* ibp = rnn_input + (size_t)b * Tt * 2 + (size_t)t * 2;
            float in0 = ibp[0], in1 = ibp[1];

            float* cp = sc + row * CSTRIDE + ub;
            float* op = out + (size_t)b * Tt * Zz + (size_t)t * Zz + 2 + nb * 16 + ub;

            float cc[8], hnv[8];
            #pragma unroll
            for (int q = 0; q < 2; q++) {
                float4 v = *(float4*)(cp + q * 4);
                cc[4*q] = v.x; cc[4*q+1] = v.y; cc[4*q+2] = v.z; cc[4*q+3] = v.w;
            }
            float s0 = 0.f, s1 = 0.f, s2 = 0.f, s3 = 0.f;
            #pragma unroll
            for (int q = 0; q < 8; q++) {
                int ul = ub + q;
                float4 bias4 = *(float4*)(sbias + ul * 4);
                float bv[4] = {bias4.x, bias4.y, bias4.z, bias4.w};
                float gv[4];
                #pragma unroll
                for (int g2 = 0; g2 < 4; g2++) {
                    float4 wf = *(float4*)(swf + (ul * 4 + g2) * 4);
                    gv[g2] = D[row * DSTRIDE + ul * 4 + g2] + bv[g2]
                           + xp0 * wf.x + xp1 * wf.y + in0 * wf.z + in1 * wf.w;
                }
                float ig = fsigm(gv[0]), fg = fsigm(gv[1]);
                float gg = ftanh(gv[2]), og = fsigm(gv[3]);
                float cn = fg * cc[q] + ig * gg;
                cc[q] = cn;
                float hn = og * ftanh(cn);
                hnv[q] = hn;
                s0 = fmaf(hn, saw[ul],      s0);
                s1 = fmaf(hn, saw[16 + ul], s1);
                s2 = fmaf(hn, saw[32 + ul], s2);
                s3 = fmaf(hn, saw[48 + ul], s3);
            }
            #pragma unroll
            for (int q = 0; q < 2; q++)
                *(float4*)(cp + q * 4) = make_float4(cc[4*q], cc[4*q+1], cc[4*q+2], cc[4*q+3]);
            #pragma unroll
            for (int q = 0; q < 4; q++)   // out row only 8B-aligned
                *(float2*)(op + q * 2) = make_float2(hnv[2*q], hnv[2*q+1]);

            s0 += __shfl_xor_sync(0xffffffffu, s0, 1);
            s1 += __shfl_xor_sync(0xffffffffu, s1, 1);
            s2 += __shfl_xor_sync(0xffffffffu, s2, 1);
            s3 += __shfl_xor_sync(0xffffffffu, s3, 1);
            if ((tid & 1) == 0) {
                atomicAdd(&g_salpha[b * 4 + 0], s0);
                atomicAdd(&g_salpha[b * 4 + 1], s1);
                atomicAdd(&g_salpha[b * 4 + 2], s2);
                atomicAdd(&g_salpha[b * 4 + 3], s3);
            }

            // next-step A image (fp16, pre-swizzled)
            int mt = b >> 6, row64 = b & 63;
            int ch = nb >> 2;
            int kc = (nb & 3) * 16 + ub;
            uint32_t rel = (uint32_t)(row64 * 128)
                         + (((uint32_t)(kc * 2)) ^ ((row64 & 7) << 4));
            __half2 hx[4];
            #pragma unroll
            for (int j = 0; j < 4; j++)
                hx[j] = __floats2half2_rn(hnv[2*j], hnv[2*j+1]);
            char* idst = (char*)g_Aimg
                       + ((size_t)(((par ^ 1) * 4 + mt) * 16 + ch) << 13) + rel;
            *(uint4*)idst = *(uint4*)hx;

            if (t == Tt - 1) {
                float* hp = g_h + (size_t)b * Hh + nb * 16 + ub;
                float* cg = g_c + (size_t)b * Hh + nb * 16 + ub;
                #pragma unroll
                for (int q = 0; q < 2; q++) {
                    *(float4*)(hp + q * 4) = make_float4(hnv[4*q], hnv[4*q+1], hnv[4*q+2], hnv[4*q+3]);
                    *(float4*)(cg + q * 4) = make_float4(cc[4*q], cc[4*q+1], cc[4*q+2], cc[4*q+3]);
                }
            }
        }

        // ---- grid barrier: REDG arrive + acquire-load polls (cumulative) ----
        __syncthreads();
        if (tid == 0) {
            __threadfence();
            asm volatile("red.release.gpu.global.add.u32 [%0], 1;"
                         :: "l"(&g_bar_arrive) : "memory");
            unsigned tgt = 128u * (unsigned)(t + 1);
            if (cta == 0) {
                unsigned v;
                do {
                    __nanosleep(32);
                    asm volatile("ld.acquire.gpu.global.u32 %0, [%1];"
                                 : "=r"(v) : "l"(&g_bar_arrive));
                } while (v < tgt);
                asm volatile("st.release.gpu.global.u32 [%0], %1;"
                             :: "l"(&g_bar_epoch), "r"((unsigned)(t + 1)) : "memory");
            } else {
                unsigned v;
                do {
                    __nanosleep(32);
                    asm volatile("ld.acquire.gpu.global.u32 %0, [%1];"
                                 : "=r"(v) : "l"(&g_bar_epoch));
                } while (v < (unsigned)(t + 1));
            }
        }
        __syncthreads();

        // ---- x update: every CTA computes its own 128 rows (redundant x64) ----
        if (tid < 128) {
            int b = m0 + tid;
            float4 C = __ldcg((const float4*)(g_salpha + b * 4));
            float4 P = *(float4*)(sprev + tid * 4);
            *(float4*)(sprev + tid * 4) = C;
            float s0 = C.x - P.x, s1 = C.y - P.y;
            float s2 = C.z - P.z, s3 = C.w - P.w;

            float x1 = sx[tid * 2], x2 = sx[tid * 2 + 1];
            float u  = rnn_input[(size_t)b * Tt * 2 + (size_t)t * 2];
            float ta = tau[(size_t)b * Tt + t];
            float a10 = -1.0f - 2.0f * x1 * x2;
            float a11 = 1.0f - x1 * x1;
            float xm0 = x1 + ta * x2;
            float xm1 = x2 + ta * (a10 * x1 + a11 * x2 + u);
            float al0 = fsigm(s0 + ab0);
            float al1 = fsigm(s1 + ab1);
            float xn0 = (1.0f - al0) * xm0 + al0 * (s2 + wb0);
            float xn1 = (1.0f - al1) * xm1 + al1 * (s3 + wb1);
            sx[tid * 2]     = xn0;
            sx[tid * 2 + 1] = xn1;

            if (nb == 0) {
                size_t ob = (size_t)b * Tt * Zz + (size_t)t * Zz;
                out[ob + 0] = xn0;
                out[ob + 1] = xn1;
                size_t cb = COEF_OFF + (size_t)b * Tt * 2 + (size_t)t * 2;
                out[cb + 0] = al0;
                out[cb + 1] = al1;
                if (b == 0) {
                    size_t mo = MATS_OFF + (size_t)t * 4;
                    out[mo + 0] = 0.0f;
                    out[mo + 1] = 1.0f;
                    out[mo + 2] = a10;
                    out[mo + 3] = a11;
                }
                if (t == Tt - 1) {
                    g_x[b * 2 + 0] = xn0;
                    g_x[b * 2 + 1] = xn1;
                }
            }
        }
        // sx/sprev writes ordered for next epilogue by the post-mainloop sync
    }
}

// ---------------------------------------------------------------------------
__global__ void finalize(const float* __restrict__ c_z0,
                         float* __restrict__ out) {
    int i = blockIdx.x * blockDim.x + threadIdx.x;
    if (i >= Bb * Zz) return;
    int b = i / Zz, z = i - b * Zz;
    float zv, cv;
    if (z < 2) {
        zv = g_x[b * 2 + z];
        cv = c_z0[(size_t)b * Zz + z];
    } else {
        zv = g_h[(size_t)b * Hh + z - 2];
        cv = g_c[(size_t)b * Hh + z - 2];
    }
    out[ZF_OFF  + i] = zv;
    out[CZF_OFF + i] = cv;
}

// ---------------------------------------------------------------------------
extern "C" void kernel_launch(void* const* d_in, const int* in_sizes, int n_in,
                              void* d_out, int out_size) {
    const float* rnn_input = (const float*)d_in[0];
    const float* tau       = (const float*)d_in[1];
    const float* z0        = (const float*)d_in[2];
    const float* c_z0      = (const float*)d_in[3];
    const float* WU_w      = (const float*)d_in[4];
    const float* WU_b      = (const float*)d_in[5];
    const float* alpha_w   = (const float*)d_in[6];
    const float* alpha_b   = (const float*)d_in[7];
    const float* Wx_w      = (const float*)d_in[8];
    const float* Wx_b      = (const float*)d_in[9];
    float* out = (float*)d_out;

    const int smem_bytes = SM_TOT + 1024 + 128;   // 212608
    cudaFuncSetAttribute(lstm_persist,
                         cudaFuncAttributeMaxDynamicSharedMemorySize, smem_bytes);

    repack<<<dim3(64, 16), 256>>>(WU_w);
    prep_misc<<<16, 256>>>(WU_w, WU_b);
    init_state<<<(Bb * Hh + 255) / 256, 256>>>(z0, c_z0);

    lstm_persist<<<128, 256, smem_bytes>>>(rnn_input, tau, alpha_w, alpha_b,
                                           Wx_w, Wx_b, out);

    finalize<<<(Bb * Zz + 127) / 128, 128>>>(c_z0, out);
}

// round 12
// speedup vs baseline: 8.6226x; 1.1776x over previous
#include <cuda_runtime.h>
#include <cuda_fp16.h>
#include <math.h>
#include <stdint.h>

#define Bb   256
#define Tt   256
#define Hh   1024
#define Zz   1026
#define KW   1028

#define ZF_OFF   ((long long)Bb * Tt * Zz)
#define CZF_OFF  (ZF_OFF + (long long)Bb * Zz)
#define COEF_OFF (CZF_OFF + (long long)Bb * Zz)
#define MATS_OFF (COEF_OFF + (long long)Bb * Tt * 2)

// Persistent device state
__device__ float g_h[Bb * Hh];                    // final h (finalize only)
__device__ float g_c[Bb * Hh];                    // init + final c
__device__ float g_x[Bb * 2];                     // init + final x
__device__ __align__(16) float g_salpha[Bb * 4];  // CUMULATIVE alpha/Wx sums
// fp16 pre-swizzled images (8KB blocks: 64 rows x 64 k, 128B rows, SW128):
__device__ __align__(128) __half g_Wimg[64 * 16 * 4096];       // [nb][ch]
__device__ __align__(128) __half g_Aimg[2 * 4 * 16 * 4096];    // [par][mt][ch]
__device__ float g_bias[4096];
__device__ float g_wfront[4096 * 4];
// grid barrier (cumulative counter, never reset)
__device__ unsigned g_bar_arrive;

// fast sigmoid/tanh via EX2+RCP (err ~1e-7, MUFU only)
__device__ __forceinline__ float fsigm(float x) {
    float e, r;
    asm("ex2.approx.f32 %0, %1;" : "=f"(e) : "f"(x * -1.442695041f));
    asm("rcp.approx.f32 %0, %1;" : "=f"(r) : "f"(1.0f + e));
    return r;
}
__device__ __forceinline__ float ftanh(float x) {
    return fmaf(2.0f, fsigm(2.0f * x), -1.0f);
}

__device__ __forceinline__ uint32_t smem_u32(const void* p) {
    uint32_t a;
    asm("{ .reg .u64 t; cvta.to.shared.u64 t, %1; cvt.u32.u64 %0, t; }" : "=r"(a) : "l"(p));
    return a;
}

__device__ __forceinline__ void ldsm4(uint32_t* r, uint32_t addr) {
    asm volatile("ldmatrix.sync.aligned.m8n8.x4.shared.b16 {%0,%1,%2,%3}, [%4];"
                 : "=r"(r[0]), "=r"(r[1]), "=r"(r[2]), "=r"(r[3]) : "r"(addr));
}

__device__ __forceinline__ void mma16816(float (&d)[4], const uint32_t* a,
                                         uint32_t b0, uint32_t b1) {
    asm volatile(
        "mma.sync.aligned.m16n8k16.row.col.f32.f16.f16.f32 "
        "{%0,%1,%2,%3}, {%4,%5,%6,%7}, {%8,%9}, {%0,%1,%2,%3};"
        : "+f"(d[0]), "+f"(d[1]), "+f"(d[2]), "+f"(d[3])
        : "r"(a[0]), "r"(a[1]), "r"(a[2]), "r"(a[3]), "r"(b0), "r"(b1));
}

#define CPA(dst, src) \
    asm volatile("cp.async.cg.shared.global [%0], [%1], 16;" \
                 :: "r"(dst), "l"(src) : "memory")
#define CPA_COMMIT() asm volatile("cp.async.commit_group;" ::: "memory")
#define CPA_WAIT0()  asm volatile("cp.async.wait_group 0;" ::: "memory")
#define CPA_WAIT3()  asm volatile("cp.async.wait_group 3;" ::: "memory")

// SMEM layout (relative to 1024-aligned base)
#define SM_B    0        // 131072: resident B (16 x 8KB)
#define SM_A    131072   // 65536: per-warp rings (8 warps x 4 x 2KB); D overlays own ring
#define SM_C    196608   // 10240: c state (128 rows x stride 20)
#define SM_MISC 206848   // 1536: bias(64f) | wfront(256f) | aw(64f)
#define SM_SX   208384   // 1024: x state (128 rows x 2)
#define SM_PREV 209408   // 2048: prev cumulative salpha (128 x 4)
#define SM_TOT  211456
#define CSTRIDE 20
#define DW      68       // per-warp D row stride (floats)

// ---------------------------------------------------------------------------
__global__ void repack(const float* __restrict__ WU_w) {
    int nb = blockIdx.x, ch = blockIdx.y;
    char* base = (char*)g_Wimg + ((size_t)(nb * 16 + ch) << 13);
    for (int e = threadIdx.x; e < 4096; e += 256) {
        int r = e >> 6, c = e & 63;
        int rg = nb * 64 + r;
        int u = rg >> 2, g = rg & 3;
        float w = WU_w[(size_t)(g * Hh + u) * KW + 4 + ch * 64 + c];
        uint32_t off = (uint32_t)(r * 128 + c * 2);
        off ^= (off >> 3) & 0x70;
        *(__half*)(base + off) = __float2half_rn(w);
    }
}

__global__ void prep_misc(const float* __restrict__ WU_w,
                          const float* __restrict__ WU_b) {
    int r = blockIdx.x * 256 + threadIdx.x;
    if (r >= 4096) return;
    int u = r >> 2, g = r & 3;
    g_bias[r] = WU_b[g * Hh + u];
    const float* src = WU_w + (size_t)(g * Hh + u) * KW;
    #pragma unroll
    for (int j = 0; j < 4; j++) g_wfront[r * 4 + j] = src[j];
}

__global__ void init_state(const float* __restrict__ z0,
                           const float* __restrict__ c_z0) {
    int i = blockIdx.x * blockDim.x + threadIdx.x;
    if (i == 0) g_bar_arrive = 0u;
    if (i < Bb * 4) g_salpha[i] = 0.0f;
    if (i < Bb * Hh) {
        int b = i / Hh, j = i - b * Hh;
        float hv = z0[(size_t)b * Zz + 2 + j];
        g_c[i] = c_z0[(size_t)b * Zz + 2 + j];
        int mt = b >> 6, row = b & 63, ch = j >> 6, kc = j & 63;
        uint32_t rel = (uint32_t)(row * 128 + kc * 2);
        rel ^= (rel >> 3) & 0x70;
        *(__half*)((char*)g_Aimg + ((size_t)(mt * 16 + ch) << 13) + rel)
            = __float2half_rn(hv);
    }
    if (i < Bb * 2) {
        int b = i >> 1, s = i & 1;
        g_x[i] = z0[(size_t)b * Zz + s];
    }
}

// stage one 2KB A slice: warp w's 16 rows of chunk ch into ring stage s
__device__ __forceinline__ void stage_w(int par, int mb, int w, int lane,
                                        uint32_t wring, int ch, int s) {
    const char* src = (const char*)g_Aimg
        + ((size_t)((par * 4 + mb * 2 + (w >> 2)) * 16 + ch) << 13)
        + (uint32_t)((w & 3) * 2048);
    uint32_t d = wring + (uint32_t)(s * 2048);
    #pragma unroll
    for (int i = 0; i < 4; i++) {
        uint32_t f = (uint32_t)((i * 32 + lane) * 16);
        CPA(d + f, src + f);
    }
}

// ---------------------------------------------------------------------------
// Persistent kernel: grid 128 (mb = cta&1, nb = cta>>1), block 256, 1 CTA/SM
// ---------------------------------------------------------------------------
__global__ __launch_bounds__(256) void lstm_persist(
    const float* __restrict__ rnn_input, const float* __restrict__ tau,
    const float* __restrict__ alpha_w,   const float* __restrict__ alpha_b,
    const float* __restrict__ Wx_w,      const float* __restrict__ Wx_b,
    float* __restrict__ out)
{
    extern __shared__ char smraw[];
    uint32_t sb0 = smem_u32(smraw);
    uint32_t pad = (1024u - (sb0 & 1023u)) & 1023u;
    char* smb = smraw + pad;
    uint32_t sb = sb0 + pad;

    int tid = threadIdx.x;
    int cta = blockIdx.x;
    int mb = cta & 1, nb = cta >> 1;
    int m0 = mb * 128;

    int w = tid >> 5, lane = tid & 31;
    uint32_t wring = sb + SM_A + ((uint32_t)w << 13);
    float* Dw = (float*)(smb + SM_A + (w << 13));
    uint32_t a_kx = (uint32_t)((lane >> 4) * 16);
    uint32_t a_xm = (uint32_t)(((lane & 15) & 7) << 4);
    uint32_t a_ro = (uint32_t)((lane & 15) * 128);
    int brow = (lane & 7) + ((lane >> 4) & 1) * 8;
    uint32_t b_kx = (uint32_t)(((lane >> 3) & 1) * 16);
    uint32_t b_xm = (uint32_t)((lane & 7) << 4);

    float* sc    = (float*)(smb + SM_C);
    float* sbias = (float*)(smb + SM_MISC);
    float* swf   = sbias + 64;
    float* saw   = swf + 256;
    float* sx    = (float*)(smb + SM_SX);
    float* sprev = (float*)(smb + SM_PREV);

    // ---- prologue ----
    {
        const char* bsrc = (const char*)g_Wimg + ((size_t)(nb * 16) << 13);
        #pragma unroll
        for (int it = 0; it < 32; it++) {
            uint32_t f = (uint32_t)((it * 256 + tid) * 16);
            CPA(sb + SM_B + f, bsrc + f);
        }
        CPA_COMMIT();
        if (tid < 64)  sbias[tid] = g_bias[nb * 64 + tid];
        swf[tid] = g_wfront[nb * 256 + tid];
        if (tid < 16) {
            saw[tid]      = alpha_w[nb * 16 + tid];
            saw[16 + tid] = alpha_w[1024 + nb * 16 + tid];
            saw[32 + tid] = Wx_w[nb * 16 + tid];
            saw[48 + tid] = Wx_w[1024 + nb * 16 + tid];
        }
        {
            int row = tid >> 1, ub = (tid & 1) * 8;
            const float* csrc = g_c + (size_t)(m0 + row) * Hh + nb * 16 + ub;
            float4 v0 = *(const float4*)csrc;
            float4 v1 = *(const float4*)(csrc + 4);
            *(float4*)(sc + row * CSTRIDE + ub)     = v0;
            *(float4*)(sc + row * CSTRIDE + ub + 4) = v1;
        }
        if (tid < 128) {
            sx[tid * 2]     = g_x[(m0 + tid) * 2];
            sx[tid * 2 + 1] = g_x[(m0 + tid) * 2 + 1];
            *(float4*)(sprev + tid * 4) = make_float4(0.f, 0.f, 0.f, 0.f);
        }
        CPA_WAIT0();
        __syncthreads();
        // initial A stages for t=0
        stage_w(0, mb, w, lane, wring, 0, 0); CPA_COMMIT();
        stage_w(0, mb, w, lane, wring, 1, 1); CPA_COMMIT();
        stage_w(0, mb, w, lane, wring, 2, 2); CPA_COMMIT();
    }
    float ab0 = alpha_b[0], ab1 = alpha_b[1];
    float wb0 = Wx_b[0],    wb1 = Wx_b[1];

    for (int t = 0; t < Tt; t++) {
        int par = t & 1;

        float acc[8][4];
        #pragma unroll
        for (int j = 0; j < 8; j++)
            #pragma unroll
            for (int q = 0; q < 4; q++) acc[j][q] = 0.0f;

        for (int c = 0; c < 16; c++) {
            if (c + 3 < 16) stage_w(par, mb, w, lane, wring, c + 3, (c + 3) & 3);
            CPA_COMMIT();
            CPA_WAIT3();
            __syncwarp();
            uint32_t abb = wring + (uint32_t)((c & 3) * 2048) + a_ro;
            uint32_t bbb = sb + SM_B + ((uint32_t)c << 13);
            #pragma unroll
            for (int kk = 0; kk < 4; kk++) {
                uint32_t kofs = (uint32_t)(kk * 32);
                uint32_t Ah[4];
                ldsm4(Ah, abb + ((a_kx + kofs) ^ a_xm));
                #pragma unroll
                for (int p = 0; p < 4; p++) {
                    uint32_t Bh[4];
                    ldsm4(Bh, bbb + (uint32_t)((p * 16 + brow) * 128)
                                  + ((b_kx + kofs) ^ b_xm));
                    mma16816(acc[2*p],     Ah, Bh[0], Bh[1]);
                    mma16816(acc[2*p + 1], Ah, Bh[2], Bh[3]);
                }
            }
        }
        CPA_WAIT0();
        __syncwarp();

        // D scratch in OWN ring (warp-local; no block sync needed)
        {
            int rl = lane >> 2;
            int c0 = (lane & 3) * 2;
            #pragma unroll
            for (int j = 0; j < 8; j++) {
                *(float2*)&Dw[rl * DW + j * 8 + c0]       = make_float2(acc[j][0], acc[j][1]);
                *(float2*)&Dw[(rl + 8) * DW + j * 8 + c0] = make_float2(acc[j][2], acc[j][3]);
            }
        }
        __syncwarp();

        // ---- fused LSTM pointwise epilogue (warp-local D) ----
        {
            int rl  = lane >> 1;           // row within warp block
            int row = w * 16 + rl;         // row within CTA tile (0..127)
            int ub  = (lane & 1) * 8;
            int b   = m0 + row;
            float xp0 = sx[row * 2], xp1 = sx[row * 2 + 1];
            const float* ibp = rnn_input + (size_t)b * Tt * 2 + (size_t)t * 2;
            float in0 = ibp[0], in1 = ibp[1];

            float* cp = sc + row * CSTRIDE + ub;
            float* op = out + (size_t)b * Tt * Zz + (size_t)t * Zz + 2 + nb * 16 + ub;

            float cc[8], hnv[8];
            #pragma unroll
            for (int q = 0; q < 2; q++) {
                float4 v = *(float4*)(cp + q * 4);
                cc[4*q] = v.x; cc[4*q+1] = v.y; cc[4*q+2] = v.z; cc[4*q+3] = v.w;
            }
            float s0 = 0.f, s1 = 0.f, s2 = 0.f, s3 = 0.f;
            #pragma unroll
            for (int q = 0; q < 8; q++) {
                int ul = ub + q;
                float4 g4 = *(float4*)(&Dw[rl * DW + ul * 4]);
                float4 bias4 = *(float4*)(sbias + ul * 4);
                float gvv[4] = {g4.x + bias4.x, g4.y + bias4.y,
                                g4.z + bias4.z, g4.w + bias4.w};
                #pragma unroll
                for (int g2 = 0; g2 < 4; g2++) {
                    float4 wf = *(float4*)(swf + (ul * 4 + g2) * 4);
                    gvv[g2] += xp0 * wf.x + xp1 * wf.y + in0 * wf.z + in1 * wf.w;
                }
                float ig = fsigm(gvv[0]), fg = fsigm(gvv[1]);
                float gg = ftanh(gvv[2]), og = fsigm(gvv[3]);
                float cn = fg * cc[q] + ig * gg;
                cc[q] = cn;
                float hn = og * ftanh(cn);
                hnv[q] = hn;
                s0 = fmaf(hn, saw[ul],      s0);
                s1 = fmaf(hn, saw[16 + ul], s1);
                s2 = fmaf(hn, saw[32 + ul], s2);
                s3 = fmaf(hn, saw[48 + ul], s3);
            }
            #pragma unroll
            for (int q = 0; q < 2; q++)
                *(float4*)(cp + q * 4) = make_float4(cc[4*q], cc[4*q+1], cc[4*q+2], cc[4*q+3]);
            #pragma unroll
            for (int q = 0; q < 4; q++)   // out row only 8B-aligned
                *(float2*)(op + q * 2) = make_float2(hnv[2*q], hnv[2*q+1]);

            s0 += __shfl_xor_sync(0xffffffffu, s0, 1);
            s1 += __shfl_xor_sync(0xffffffffu, s1, 1);
            s2 += __shfl_xor_sync(0xffffffffu, s2, 1);
            s3 += __shfl_xor_sync(0xffffffffu, s3, 1);
            if ((lane & 1) == 0) {
                atomicAdd(&g_salpha[b * 4 + 0], s0);
                atomicAdd(&g_salpha[b * 4 + 1], s1);
                atomicAdd(&g_salpha[b * 4 + 2], s2);
                atomicAdd(&g_salpha[b * 4 + 3], s3);
            }

            // next-step A image (fp16, pre-swizzled)
            int mt = b >> 6, row64 = b & 63;
            int ch = nb >> 2;
            int kc = (nb & 3) * 16 + ub;
            uint32_t rel = (uint32_t)(row64 * 128)
                         + (((uint32_t)(kc * 2)) ^ ((row64 & 7) << 4));
            __half2 hx[4];
            #pragma unroll
            for (int j = 0; j < 4; j++)
                hx[j] = __floats2half2_rn(hnv[2*j], hnv[2*j+1]);
            char* idst = (char*)g_Aimg
                       + ((size_t)(((par ^ 1) * 4 + mt) * 16 + ch) << 13) + rel;
            *(uint4*)idst = *(uint4*)hx;

            if (t == Tt - 1) {
                float* hp = g_h + (size_t)b * Hh + nb * 16 + ub;
                float* cg = g_c + (size_t)b * Hh + nb * 16 + ub;
                #pragma unroll
                for (int q = 0; q < 2; q++) {
                    *(float4*)(hp + q * 4) = make_float4(hnv[4*q], hnv[4*q+1], hnv[4*q+2], hnv[4*q+3]);
                    *(float4*)(cg + q * 4) = make_float4(cc[4*q], cc[4*q+1], cc[4*q+2], cc[4*q+3]);
                }
            }
        }

        // ---- one-hop grid barrier: cumulative arrive, all CTAs poll it ----
        __syncthreads();
        if (tid == 0) {
            __threadfence();
            asm volatile("red.release.gpu.global.add.u32 [%0], 1;"
                         :: "l"(&g_bar_arrive) : "memory");
            unsigned tgt = 128u * (unsigned)(t + 1);
            unsigned v;
            do {
                asm volatile("ld.acquire.gpu.global.u32 %0, [%1];"
                             : "=r"(v) : "l"(&g_bar_arrive));
                if (v >= tgt) break;
                __nanosleep(16);
            } while (1);
        }
        __syncthreads();

        // stage next step's first chunks IMMEDIATELY (A image now ready)
        if (t + 1 < Tt) {
            stage_w(par ^ 1, mb, w, lane, wring, 0, 0); CPA_COMMIT();
            stage_w(par ^ 1, mb, w, lane, wring, 1, 1); CPA_COMMIT();
            stage_w(par ^ 1, mb, w, lane, wring, 2, 2); CPA_COMMIT();
        }

        // ---- x update (overlaps staging flight) ----
        if (tid < 128) {
            int b = m0 + tid;
            float4 C = __ldcg((const float4*)(g_salpha + b * 4));
            float4 P = *(float4*)(sprev + tid * 4);
            *(float4*)(sprev + tid * 4) = C;
            float s0 = C.x - P.x, s1 = C.y - P.y;
            float s2 = C.z - P.z, s3 = C.w - P.w;

            float x1 = sx[tid * 2], x2 = sx[tid * 2 + 1];
            float u  = rnn_input[(size_t)b * Tt * 2 + (size_t)t * 2];
            float ta = tau[(size_t)b * Tt + t];
            float a10 = -1.0f - 2.0f * x1 * x2;
            float a11 = 1.0f - x1 * x1;
            float xm0 = x1 + ta * x2;
            float xm1 = x2 + ta * (a10 * x1 + a11 * x2 + u);
            float al0 = fsigm(s0 + ab0);
            float al1 = fsigm(s1 + ab1);
            float xn0 = (1.0f - al0) * xm0 + al0 * (s2 + wb0);
            float xn1 = (1.0f - al1) * xm1 + al1 * (s3 + wb1);
            sx[tid * 2]     = xn0;
            sx[tid * 2 + 1] = xn1;

            if (nb == 0) {
                size_t ob = (size_t)b * Tt * Zz + (size_t)t * Zz;
                out[ob + 0] = xn0;
                out[ob + 1] = xn1;
                size_t cb = COEF_OFF + (size_t)b * Tt * 2 + (size_t)t * 2;
                out[cb + 0] = al0;
                out[cb + 1] = al1;
                if (b == 0) {
                    size_t mo = MATS_OFF + (size_t)t * 4;
                    out[mo + 0] = 0.0f;
                    out[mo + 1] = 1.0f;
                    out[mo + 2] = a10;
                    out[mo + 3] = a11;
                }
                if (t == Tt - 1) {
                    g_x[b * 2 + 0] = xn0;
                    g_x[b * 2 + 1] = xn1;
                }
            }
        }
        __syncthreads();   // sx/sprev visible to all before next epilogue
    }
}

// ---------------------------------------------------------------------------
__global__ void finalize(const float* __restrict__ c_z0,
                         float* __restrict__ out) {
    int i = blockIdx.x * blockDim.x + threadIdx.x;
    if (i >= Bb * Zz) return;
    int b = i / Zz, z = i - b * Zz;
    float zv, cv;
    if (z < 2) {
        zv = g_x[b * 2 + z];
        cv = c_z0[(size_t)b * Zz + z];
    } else {
        zv = g_h[(size_t)b * Hh + z - 2];
        cv = g_c[(size_t)b * Hh + z - 2];
    }
    out[ZF_OFF  + i] = zv;
    out[CZF_OFF + i] = cv;
}

// ---------------------------------------------------------------------------
extern "C" void kernel_launch(void* const* d_in, const int* in_sizes, int n_in,
                              void* d_out, int out_size) {
    const float* rnn_input = (const float*)d_in[0];
    const float* tau       = (const float*)d_in[1];
    const float* z0        = (const float*)d_in[2];
    const float* c_z0      = (const float*)d_in[3];
    const float* WU_w      = (const float*)d_in[4];
    const float* WU_b      = (const float*)d_in[5];
    const float* alpha_w   = (const float*)d_in[6];
    const float* alpha_b   = (const float*)d_in[7];
    const float* Wx_w      = (const float*)d_in[8];
    const float* Wx_b      = (const float*)d_in[9];
    float* out = (float*)d_out;

    const int smem_bytes = SM_TOT + 1024 + 128;   // 212608
    cudaFuncSetAttribute(lstm_persist,
                         cudaFuncAttributeMaxDynamicSharedMemorySize, smem_bytes);

    repack<<<dim3(64, 16), 256>>>(WU_w);
    prep_misc<<<16, 256>>>(WU_w, WU_b);
    init_state<<<(Bb * Hh + 255) / 256, 256>>>(z0, c_z0);

    lstm_persist<<<128, 256, smem_bytes>>>(rnn_input, tau, alpha_w, alpha_b,
                                           Wx_w, Wx_b, out);

    finalize<<<(Bb * Zz + 127) / 128, 128>>>(c_z0, out);
}